// round 1
// baseline (speedup 1.0000x reference)
#include <cuda_runtime.h>

#define Bb 4
#define Tt 2048
#define Cc 1024
#define NHh 16
#define Dd 64

// Scratch (static device globals — allocation-free at launch time)
__device__ float g_qkv[(size_t)Bb * Tt * 3 * Cc];   // [B,T,3C]  ~100.7 MB
__device__ float g_att[(size_t)Bb * Tt * Cc];       // [B,T,C]   ~33.6 MB

// ---------------------------------------------------------------------------
// SGEMM (NT): C[M,N] = A[M,K] @ B[N,K]^T + bias[N]
// BM=128, BN=64, BK=16, 256 threads, 8x4 microtile per thread.
// MODE 0: A = param (x), C = g_qkv.   MODE 1: A = g_att, C = param (d_out).
// ---------------------------------------------------------------------------
template <int MODE>
__global__ __launch_bounds__(256) void sgemm_nt(
    const float* __restrict__ Ap, const float* __restrict__ Bw,
    const float* __restrict__ bias, float* __restrict__ Cp,
    int M, int N, int K)
{
    const float* A = (MODE == 0) ? Ap : g_att;
    float* C       = (MODE == 0) ? g_qkv : Cp;

    constexpr int BM = 128, BN = 64, BK = 16;
    __shared__ float As[BK][BM];   // transposed: As[k][m]
    __shared__ float Bs[BK][BN];   // transposed: Bs[k][n]

    const int tid = threadIdx.x;
    const int tx  = tid & 15;   // n-direction (16)
    const int ty  = tid >> 4;   // m-direction (16)
    const int m0  = blockIdx.y * BM;
    const int n0  = blockIdx.x * BN;

    float acc[8][4];
#pragma unroll
    for (int i = 0; i < 8; i++)
#pragma unroll
        for (int j = 0; j < 4; j++) acc[i][j] = 0.f;

    for (int k0 = 0; k0 < K; k0 += BK) {
        // A tile: 128x16 floats = 512 float4, 2 per thread
#pragma unroll
        for (int it = 0; it < 2; it++) {
            int li = tid + it * 256;
            int m  = li >> 2;
            int c  = (li & 3) * 4;
            float4 v = *(const float4*)(A + (size_t)(m0 + m) * K + k0 + c);
            As[c + 0][m] = v.x; As[c + 1][m] = v.y;
            As[c + 2][m] = v.z; As[c + 3][m] = v.w;
        }
        // B tile: 64x16 floats = 256 float4, 1 per thread
        {
            int n = tid >> 2;
            int c = (tid & 3) * 4;
            float4 v = *(const float4*)(Bw + (size_t)(n0 + n) * K + k0 + c);
            Bs[c + 0][n] = v.x; Bs[c + 1][n] = v.y;
            Bs[c + 2][n] = v.z; Bs[c + 3][n] = v.w;
        }
        __syncthreads();

#pragma unroll
        for (int k = 0; k < BK; k++) {
            float4 a0 = *(const float4*)&As[k][ty * 8];
            float4 a1 = *(const float4*)&As[k][ty * 8 + 4];
            float4 b0 = *(const float4*)&Bs[k][tx * 4];
            float a[8] = {a0.x, a0.y, a0.z, a0.w, a1.x, a1.y, a1.z, a1.w};
            float b[4] = {b0.x, b0.y, b0.z, b0.w};
#pragma unroll
            for (int i = 0; i < 8; i++)
#pragma unroll
                for (int j = 0; j < 4; j++)
                    acc[i][j] = fmaf(a[i], b[j], acc[i][j]);
        }
        __syncthreads();
    }

    float bv[4];
#pragma unroll
    for (int j = 0; j < 4; j++) bv[j] = bias[n0 + tx * 4 + j];
#pragma unroll
    for (int i = 0; i < 8; i++) {
        float4 v;
        v.x = acc[i][0] + bv[0];
        v.y = acc[i][1] + bv[1];
        v.z = acc[i][2] + bv[2];
        v.w = acc[i][3] + bv[3];
        *(float4*)(C + (size_t)(m0 + ty * 8 + i) * N + n0 + tx * 4) = v;
    }
}

// ---------------------------------------------------------------------------
// RoPE in-place on q,k halves of g_qkv.
// One thread per (b,t,h,d2), d2 in [0,32): handles the (d2, d2+32) pair
// for both q and k.
// ---------------------------------------------------------------------------
__global__ void rope_kernel(const float* __restrict__ cosp,
                            const float* __restrict__ sinp)
{
    int idx = blockIdx.x * blockDim.x + threadIdx.x;
    int d2 = idx & 31;
    int h  = (idx >> 5) & 15;
    int t  = (idx >> 9) & 2047;
    int b  = idx >> 20;

    float c = cosp[t * Dd + d2];   // cos[t,d2] == cos[t,d2+32]
    float s = sinp[t * Dd + d2];

    size_t base = ((size_t)(b * Tt + t)) * (3 * Cc) + h * Dd;
    float* qp = g_qkv + base;
    float* kp = g_qkv + base + Cc;

    float q1 = qp[d2], q2 = qp[d2 + 32];
    qp[d2]      = q1 * c - q2 * s;
    qp[d2 + 32] = q2 * c + q1 * s;

    float k1 = kp[d2], k2 = kp[d2 + 32];
    kp[d2]      = k1 * c - k2 * s;
    kp[d2 + 32] = k2 * c + k1 * s;
}

// ---------------------------------------------------------------------------
// Causal flash attention, fp32.
// Grid: (T/64, B*NH). Block: 256 threads.
// Each CTA: one (b,h) pair, 64 q rows. 4-lane group per q row; each lane
// owns a 16-wide d slice. K/V tiles (64x64) staged in smem. Online softmax.
// Heavy q-tiles scheduled first via reversed blockIdx.x.
// ---------------------------------------------------------------------------
__global__ __launch_bounds__(256, 2) void flash_attn()
{
    __shared__ float Ks[64][64];
    __shared__ float Vs[64][64];

    const int bh = blockIdx.y;
    const int b  = bh >> 4;
    const int h  = bh & 15;
    const int qt = (gridDim.x - 1) - blockIdx.x;   // heavy tiles first
    const int q0 = qt * 64;

    const int tid = threadIdx.x;
    const int r   = tid >> 2;        // local q row 0..63
    const int d0  = (tid & 3) * 16;  // d slice
    const int tq  = q0 + r;

    // Load q row slice, pre-scaled by 1/sqrt(D)
    float q[16];
    {
        const float* qptr =
            g_qkv + ((size_t)(b * Tt + tq)) * (3 * Cc) + h * Dd + d0;
        const float scale = 0.125f;
#pragma unroll
        for (int i = 0; i < 4; i++) {
            float4 v = *(const float4*)(qptr + i * 4);
            q[i * 4 + 0] = v.x * scale;
            q[i * 4 + 1] = v.y * scale;
            q[i * 4 + 2] = v.z * scale;
            q[i * 4 + 3] = v.w * scale;
        }
    }

    float o[16];
#pragma unroll
    for (int i = 0; i < 16; i++) o[i] = 0.f;
    float m = -1e30f, l = 0.f;

    for (int jt = 0; jt <= qt; jt++) {
        const int j0 = jt * 64;
        // Stage K,V tiles
        {
            const int   lr  = tid >> 2;
            const int   ld0 = (tid & 3) * 16;
            const float* kptr =
                g_qkv + ((size_t)(b * Tt + j0 + lr)) * (3 * Cc) + Cc + h * Dd + ld0;
            const float* vptr = kptr + Cc;
#pragma unroll
            for (int i = 0; i < 4; i++) {
                *(float4*)&Ks[lr][ld0 + i * 4] = *(const float4*)(kptr + i * 4);
                *(float4*)&Vs[lr][ld0 + i * 4] = *(const float4*)(vptr + i * 4);
            }
        }
        __syncthreads();

        const bool diag = (jt == qt);
        float s[64];
        float tmax = -1e30f;
#pragma unroll
        for (int j = 0; j < 64; j++) {
            const float4* kp = (const float4*)&Ks[j][d0];
            float4 k0 = kp[0], k1 = kp[1], k2 = kp[2], k3 = kp[3];
            float acc;
            acc  = q[0]  * k0.x; acc = fmaf(q[1],  k0.y, acc);
            acc  = fmaf(q[2],  k0.z, acc); acc = fmaf(q[3],  k0.w, acc);
            acc  = fmaf(q[4],  k1.x, acc); acc = fmaf(q[5],  k1.y, acc);
            acc  = fmaf(q[6],  k1.z, acc); acc = fmaf(q[7],  k1.w, acc);
            acc  = fmaf(q[8],  k2.x, acc); acc = fmaf(q[9],  k2.y, acc);
            acc  = fmaf(q[10], k2.z, acc); acc = fmaf(q[11], k2.w, acc);
            acc  = fmaf(q[12], k3.x, acc); acc = fmaf(q[13], k3.y, acc);
            acc  = fmaf(q[14], k3.z, acc); acc = fmaf(q[15], k3.w, acc);
            acc += __shfl_xor_sync(0xffffffff, acc, 1);
            acc += __shfl_xor_sync(0xffffffff, acc, 2);
            if (diag && (j0 + j) > tq) acc = -1e30f;
            s[j] = acc;
            tmax = fmaxf(tmax, acc);
        }

        float mnew  = fmaxf(m, tmax);
        float alpha = __expf(m - mnew);
        l *= alpha;
#pragma unroll
        for (int i = 0; i < 16; i++) o[i] *= alpha;

#pragma unroll
        for (int j = 0; j < 64; j++) {
            float p = __expf(s[j] - mnew);
            l += p;
            const float4* vp = (const float4*)&Vs[j][d0];
            float4 v0 = vp[0], v1 = vp[1], v2 = vp[2], v3 = vp[3];
            o[0]  = fmaf(p, v0.x, o[0]);  o[1]  = fmaf(p, v0.y, o[1]);
            o[2]  = fmaf(p, v0.z, o[2]);  o[3]  = fmaf(p, v0.w, o[3]);
            o[4]  = fmaf(p, v1.x, o[4]);  o[5]  = fmaf(p, v1.y, o[5]);
            o[6]  = fmaf(p, v1.z, o[6]);  o[7]  = fmaf(p, v1.w, o[7]);
            o[8]  = fmaf(p, v2.x, o[8]);  o[9]  = fmaf(p, v2.y, o[9]);
            o[10] = fmaf(p, v2.z, o[10]); o[11] = fmaf(p, v2.w, o[11]);
            o[12] = fmaf(p, v3.x, o[12]); o[13] = fmaf(p, v3.y, o[13]);
            o[14] = fmaf(p, v3.z, o[14]); o[15] = fmaf(p, v3.w, o[15]);
        }
        m = mnew;
        __syncthreads();
    }

    const float inv = 1.f / l;
    float* optr = g_att + ((size_t)(b * Tt + tq)) * Cc + h * Dd + d0;
#pragma unroll
    for (int i = 0; i < 4; i++) {
        float4 v;
        v.x = o[i * 4 + 0] * inv;
        v.y = o[i * 4 + 1] * inv;
        v.z = o[i * 4 + 2] * inv;
        v.w = o[i * 4 + 3] * inv;
        *(float4*)(optr + i * 4) = v;
    }
}

// ---------------------------------------------------------------------------
extern "C" void kernel_launch(void* const* d_in, const int* in_sizes, int n_in,
                              void* d_out, int out_size)
{
    const float* x      = (const float*)d_in[0];
    const float* w_attn = (const float*)d_in[1];
    const float* b_attn = (const float*)d_in[2];
    const float* w_proj = (const float*)d_in[3];
    const float* b_proj = (const float*)d_in[4];
    const float* cosp   = (const float*)d_in[5];
    const float* sinp   = (const float*)d_in[6];
    float* out = (float*)d_out;

    const int M = Bb * Tt;  // 8192

    // 1) QKV projection: g_qkv = x @ w_attn^T + b_attn
    {
        dim3 grid((3 * Cc) / 64, M / 128);
        sgemm_nt<0><<<grid, 256>>>(x, w_attn, b_attn, nullptr, M, 3 * Cc, Cc);
    }
    // 2) RoPE on q,k (in place)
    {
        int total = Bb * Tt * NHh * (Dd / 2);  // 4,194,304
        rope_kernel<<<total / 256, 256>>>(cosp, sinp);
    }
    // 3) Causal flash attention -> g_att
    {
        dim3 grid(Tt / 64, Bb * NHh);
        flash_attn<<<grid, 256>>>();
    }
    // 4) Output projection: out = g_att @ w_proj^T + b_proj
    {
        dim3 grid(Cc / 64, M / 128);
        sgemm_nt<1><<<grid, 256>>>(nullptr, w_proj, b_proj, out, M, Cc, Cc);
    }
}

// round 3
// speedup vs baseline: 1.7060x; 1.7060x over previous
#include <cuda_runtime.h>
#include <cuda_bf16.h>
#include <cstdint>

#define Bb 4
#define Tt 2048
#define Cc 1024
#define NHh 16
#define Dd 64
#define Mtot (Bb * Tt)   // 8192

// ------------------------- scratch (__device__ globals) --------------------
__device__ float g_qkv[(size_t)Bb * Tt * 3 * Cc];    // [B,T,3C] fp32
__device__ float g_att[(size_t)Bb * Tt * Cc];        // [B,T,C]  fp32
__device__ __nv_bfloat16 g_xh[(size_t)Mtot * Cc];
__device__ __nv_bfloat16 g_xl[(size_t)Mtot * Cc];
__device__ __nv_bfloat16 g_wh[(size_t)3 * Cc * Cc];
__device__ __nv_bfloat16 g_wl[(size_t)3 * Cc * Cc];
__device__ __nv_bfloat16 g_ph[(size_t)Cc * Cc];
__device__ __nv_bfloat16 g_pl[(size_t)Cc * Cc];
__device__ __nv_bfloat16 g_ah[(size_t)Mtot * Cc];
__device__ __nv_bfloat16 g_al[(size_t)Mtot * Cc];

// ------------------------- warp-mma helpers --------------------------------
__device__ __forceinline__ uint32_t smem_u32(const void* p) {
    uint32_t a;
    asm("{ .reg .u64 t; cvta.to.shared.u64 t, %1; cvt.u32.u64 %0, t; }"
        : "=r"(a) : "l"(p));
    return a;
}

__device__ __forceinline__ void ldmx4(uint32_t& r0, uint32_t& r1,
                                      uint32_t& r2, uint32_t& r3, uint32_t addr) {
    asm volatile("ldmatrix.sync.aligned.m8n8.x4.shared.b16 {%0,%1,%2,%3}, [%4];"
                 : "=r"(r0), "=r"(r1), "=r"(r2), "=r"(r3) : "r"(addr));
}

__device__ __forceinline__ void mma16816(float* d, const uint32_t* a,
                                         uint32_t b0, uint32_t b1) {
    asm volatile(
        "mma.sync.aligned.m16n8k16.row.col.f32.bf16.bf16.f32 "
        "{%0,%1,%2,%3}, {%4,%5,%6,%7}, {%8,%9}, {%0,%1,%2,%3};"
        : "+f"(d[0]), "+f"(d[1]), "+f"(d[2]), "+f"(d[3])
        : "r"(a[0]), "r"(a[1]), "r"(a[2]), "r"(a[3]), "r"(b0), "r"(b1));
}

// ---------------------------------------------------------------------------
// bf16x3 GEMM via mma.sync: C[M,N] = (Ah+Al)[M,K] @ (Bh+Bl)[N,K]^T + bias[N]
// CTA tile 128x128, BK=32. 8 warps (2m x 4n), warp tile 64x32.
// ---------------------------------------------------------------------------
#define SPAD 40   // smem row stride in bf16 (32 data + 8 pad) = 80B
__global__ __launch_bounds__(256, 1)
void gemm_bf16x3(const __nv_bfloat16* __restrict__ Ah,
                 const __nv_bfloat16* __restrict__ Al,
                 const __nv_bfloat16* __restrict__ Bh,
                 const __nv_bfloat16* __restrict__ Bl,
                 const float* __restrict__ bias,
                 float* __restrict__ Cout, int N, int K)
{
    __shared__ __nv_bfloat16 sAh[128 * SPAD];
    __shared__ __nv_bfloat16 sAl[128 * SPAD];
    __shared__ __nv_bfloat16 sBh[128 * SPAD];
    __shared__ __nv_bfloat16 sBl[128 * SPAD];

    const int tid  = threadIdx.x;
    const int wid  = tid >> 5;
    const int lane = tid & 31;
    const int mw   = wid >> 2;      // 0..1
    const int nw   = wid & 3;       // 0..3
    const int m0   = blockIdx.y * 128;
    const int n0   = blockIdx.x * 128;

    const uint32_t uAh = smem_u32(sAh), uAl = smem_u32(sAl);
    const uint32_t uBh = smem_u32(sBh), uBl = smem_u32(sBl);

    // per-lane ldmatrix base offsets (bytes), before ks term
    const int lrow = lane & 15;
    const int lk   = (lane >> 4) * 8;  // bf16 units
    uint32_t aoff[4], boff[2];
#pragma unroll
    for (int mt = 0; mt < 4; mt++)
        aoff[mt] = (uint32_t)(((mw * 64 + mt * 16 + lrow) * SPAD + lk) * 2);
#pragma unroll
    for (int ng = 0; ng < 2; ng++)
        boff[ng] = (uint32_t)(((nw * 32 + ng * 16 + lrow) * SPAD + lk) * 2);

    float acc[4][4][4];
#pragma unroll
    for (int i = 0; i < 4; i++)
#pragma unroll
        for (int j = 0; j < 4; j++)
#pragma unroll
            for (int e = 0; e < 4; e++) acc[i][j][e] = 0.f;

    const int kq = K >> 3;          // global row stride in uint4
    const int nk = K >> 5;          // 32-wide chunks

    const int r0i = tid >> 2, c0i = tid & 3;           // load coords (i=0)
    const int r1i = (tid + 256) >> 2, c1i = tid & 3;   // i=1

    for (int kc = 0; kc < nk; kc++) {
        __syncthreads();
        {
            const size_t ab = ((size_t)m0) * kq + kc * 4;
            const size_t bb = ((size_t)n0) * kq + kc * 4;
            uint4* s;
            // i = 0 (rows 0..63), i = 1 (rows 64..127)
            s = (uint4*)sAh;
            s[r0i * 5 + c0i] = ((const uint4*)Ah)[ab + (size_t)r0i * kq + c0i];
            s[r1i * 5 + c1i] = ((const uint4*)Ah)[ab + (size_t)r1i * kq + c1i];
            s = (uint4*)sAl;
            s[r0i * 5 + c0i] = ((const uint4*)Al)[ab + (size_t)r0i * kq + c0i];
            s[r1i * 5 + c1i] = ((const uint4*)Al)[ab + (size_t)r1i * kq + c1i];
            s = (uint4*)sBh;
            s[r0i * 5 + c0i] = ((const uint4*)Bh)[bb + (size_t)r0i * kq + c0i];
            s[r1i * 5 + c1i] = ((const uint4*)Bh)[bb + (size_t)r1i * kq + c1i];
            s = (uint4*)sBl;
            s[r0i * 5 + c0i] = ((const uint4*)Bl)[bb + (size_t)r0i * kq + c0i];
            s[r1i * 5 + c1i] = ((const uint4*)Bl)[bb + (size_t)r1i * kq + c1i];
        }
        __syncthreads();

#pragma unroll
        for (int ks = 0; ks < 2; ks++) {
            const uint32_t kb = ks * 32;  // 16 bf16 = 32 bytes
            uint32_t ah[4][4], al[4][4];
#pragma unroll
            for (int mt = 0; mt < 4; mt++) {
                ldmx4(ah[mt][0], ah[mt][1], ah[mt][2], ah[mt][3], uAh + aoff[mt] + kb);
                ldmx4(al[mt][0], al[mt][1], al[mt][2], al[mt][3], uAl + aoff[mt] + kb);
            }
            uint32_t bh[2][4], bl[2][4];
#pragma unroll
            for (int ng = 0; ng < 2; ng++) {
                ldmx4(bh[ng][0], bh[ng][1], bh[ng][2], bh[ng][3], uBh + boff[ng] + kb);
                ldmx4(bl[ng][0], bl[ng][1], bl[ng][2], bl[ng][3], uBl + boff[ng] + kb);
            }
#pragma unroll
            for (int mt = 0; mt < 4; mt++) {
#pragma unroll
                for (int ng = 0; ng < 2; ng++) {
#pragma unroll
                    for (int sub = 0; sub < 2; sub++) {
                        const int nt = ng * 2 + sub;
                        const uint32_t bh0 = bh[ng][sub], bh1 = bh[ng][sub + 2];
                        const uint32_t bl0 = bl[ng][sub], bl1 = bl[ng][sub + 2];
                        mma16816(acc[mt][nt], ah[mt], bh0, bh1);
                        mma16816(acc[mt][nt], ah[mt], bl0, bl1);
                        mma16816(acc[mt][nt], al[mt], bh0, bh1);
                    }
                }
            }
        }
    }

    // Epilogue
    const int erow = lane >> 2;          // 0..7
    const int ecol = (lane & 3) * 2;     // 0,2,4,6
#pragma unroll
    for (int mt = 0; mt < 4; mt++) {
#pragma unroll
        for (int nt = 0; nt < 4; nt++) {
            const int row = m0 + mw * 64 + mt * 16 + erow;
            const int col = n0 + nw * 32 + nt * 8 + ecol;
            const float b0 = bias[col], b1 = bias[col + 1];
            float2 v;
            v.x = acc[mt][nt][0] + b0;
            v.y = acc[mt][nt][1] + b1;
            *(float2*)(Cout + (size_t)row * N + col) = v;
            v.x = acc[mt][nt][2] + b0;
            v.y = acc[mt][nt][3] + b1;
            *(float2*)(Cout + (size_t)(row + 8) * N + col) = v;
        }
    }
}

// ---------------------------------------------------------------------------
// fp32 -> (hi,lo) bf16 split, vectorized by 4
// ---------------------------------------------------------------------------
__global__ void split_fp32_bf16(const float4* __restrict__ src,
                                __nv_bfloat162* __restrict__ hi,
                                __nv_bfloat162* __restrict__ lo, int n4)
{
    int i = blockIdx.x * 256 + threadIdx.x;
    if (i >= n4) return;
    float4 v = src[i];
    __nv_bfloat16 hx = __float2bfloat16(v.x);
    __nv_bfloat16 hy = __float2bfloat16(v.y);
    __nv_bfloat16 hz = __float2bfloat16(v.z);
    __nv_bfloat16 hw = __float2bfloat16(v.w);
    __nv_bfloat16 lx = __float2bfloat16(v.x - __bfloat162float(hx));
    __nv_bfloat16 ly = __float2bfloat16(v.y - __bfloat162float(hy));
    __nv_bfloat16 lz = __float2bfloat16(v.z - __bfloat162float(hz));
    __nv_bfloat16 lw = __float2bfloat16(v.w - __bfloat162float(hw));
    __nv_bfloat162 a;
    a.x = hx; a.y = hy; hi[2 * i] = a;
    a.x = hz; a.y = hw; hi[2 * i + 1] = a;
    a.x = lx; a.y = ly; lo[2 * i] = a;
    a.x = lz; a.y = lw; lo[2 * i + 1] = a;
}

// ---------------------------------------------------------------------------
// RoPE in-place on q,k halves of g_qkv
// ---------------------------------------------------------------------------
__global__ void rope_kernel(const float* __restrict__ cosp,
                            const float* __restrict__ sinp)
{
    int idx = blockIdx.x * blockDim.x + threadIdx.x;
    int d2 = idx & 31;
    int h  = (idx >> 5) & 15;
    int t  = (idx >> 9) & 2047;
    int b  = idx >> 20;

    float c = cosp[t * Dd + d2];
    float s = sinp[t * Dd + d2];

    size_t base = ((size_t)(b * Tt + t)) * (3 * Cc) + h * Dd;
    float* qp = g_qkv + base;
    float* kp = g_qkv + base + Cc;

    float q1 = qp[d2], q2 = qp[d2 + 32];
    qp[d2]      = q1 * c - q2 * s;
    qp[d2 + 32] = q2 * c + q1 * s;

    float k1 = kp[d2], k2 = kp[d2 + 32];
    kp[d2]      = k1 * c - k2 * s;
    kp[d2 + 32] = k2 * c + k1 * s;
}

// ---------------------------------------------------------------------------
// Causal flash attention, fp32. CTA = 128 q rows, 256 threads.
// Each thread: 2 q rows x 16-wide d slice (4 lanes per row-pair).
// j tiles of 32, K/V staged in smem, K/V LDS shared across the 2 rows.
// ---------------------------------------------------------------------------
__global__ __launch_bounds__(256, 1) void flash_attn()
{
    __shared__ float Ks[32][64];
    __shared__ float Vs[32][64];

    const int bh = blockIdx.y;
    const int b  = bh >> 4;
    const int h  = bh & 15;
    const int qt = (gridDim.x - 1) - blockIdx.x;   // heavy tiles first
    const int q0 = qt * 128;

    const int tid = threadIdx.x;
    const int pr  = tid >> 2;         // row pair 0..63
    const int d0  = (tid & 3) * 16;   // d slice
    const int tq0 = q0 + pr * 2;
    const int tq1 = tq0 + 1;

    float qa[16], qb[16];
    {
        const float scale = 0.125f;
        const float* p0 = g_qkv + ((size_t)(b * Tt + tq0)) * (3 * Cc) + h * Dd + d0;
        const float* p1 = p0 + 3 * Cc;
#pragma unroll
        for (int i = 0; i < 4; i++) {
            float4 v0 = *(const float4*)(p0 + i * 4);
            float4 v1 = *(const float4*)(p1 + i * 4);
            qa[i * 4 + 0] = v0.x * scale; qa[i * 4 + 1] = v0.y * scale;
            qa[i * 4 + 2] = v0.z * scale; qa[i * 4 + 3] = v0.w * scale;
            qb[i * 4 + 0] = v1.x * scale; qb[i * 4 + 1] = v1.y * scale;
            qb[i * 4 + 2] = v1.z * scale; qb[i * 4 + 3] = v1.w * scale;
        }
    }

    float oa[16], ob[16];
#pragma unroll
    for (int i = 0; i < 16; i++) { oa[i] = 0.f; ob[i] = 0.f; }
    float m0 = -1e30f, m1 = -1e30f, l0 = 0.f, l1 = 0.f;

    const int njt = (q0 + 128) >> 5;
    for (int jt = 0; jt < njt; jt++) {
        const int j0 = jt << 5;
        for (int idx = tid; idx < 512; idx += 256) {
            int r = idx >> 4;
            int c = (idx & 15) * 4;
            const float* kp =
                g_qkv + ((size_t)(b * Tt + j0 + r)) * (3 * Cc) + Cc + h * Dd + c;
            *(float4*)&Ks[r][c] = *(const float4*)kp;
            *(float4*)&Vs[r][c] = *(const float4*)(kp + Cc);
        }
        __syncthreads();

        float s0[32], s1[32];
        float tm0 = -1e30f, tm1 = -1e30f;
#pragma unroll
        for (int j = 0; j < 32; j++) {
            float kv[16];
            *(float4*)&kv[0]  = *(const float4*)&Ks[j][d0];
            *(float4*)&kv[4]  = *(const float4*)&Ks[j][d0 + 4];
            *(float4*)&kv[8]  = *(const float4*)&Ks[j][d0 + 8];
            *(float4*)&kv[12] = *(const float4*)&Ks[j][d0 + 12];
            float a0 = 0.f, a1 = 0.f;
#pragma unroll
            for (int e = 0; e < 16; e++) {
                a0 = fmaf(qa[e], kv[e], a0);
                a1 = fmaf(qb[e], kv[e], a1);
            }
            a0 += __shfl_xor_sync(0xffffffff, a0, 1);
            a0 += __shfl_xor_sync(0xffffffff, a0, 2);
            a1 += __shfl_xor_sync(0xffffffff, a1, 1);
            a1 += __shfl_xor_sync(0xffffffff, a1, 2);
            int jj = j0 + j;
            if (jj > tq0) a0 = -1e30f;
            if (jj > tq1) a1 = -1e30f;
            s0[j] = a0; s1[j] = a1;
            tm0 = fmaxf(tm0, a0);
            tm1 = fmaxf(tm1, a1);
        }

        float m0n = fmaxf(m0, tm0);
        float m1n = fmaxf(m1, tm1);
        float al0 = __expf(m0 - m0n);
        float al1 = __expf(m1 - m1n);
        l0 *= al0; l1 *= al1;
#pragma unroll
        for (int i = 0; i < 16; i++) { oa[i] *= al0; ob[i] *= al1; }

#pragma unroll
        for (int j = 0; j < 32; j++) {
            float p0 = __expf(s0[j] - m0n);
            float p1 = __expf(s1[j] - m1n);
            l0 += p0; l1 += p1;
            float vv[16];
            *(float4*)&vv[0]  = *(const float4*)&Vs[j][d0];
            *(float4*)&vv[4]  = *(const float4*)&Vs[j][d0 + 4];
            *(float4*)&vv[8]  = *(const float4*)&Vs[j][d0 + 8];
            *(float4*)&vv[12] = *(const float4*)&Vs[j][d0 + 12];
#pragma unroll
            for (int e = 0; e < 16; e++) {
                oa[e] = fmaf(p0, vv[e], oa[e]);
                ob[e] = fmaf(p1, vv[e], ob[e]);
            }
        }
        m0 = m0n; m1 = m1n;
        __syncthreads();
    }

    const float inv0 = 1.f / l0;
    const float inv1 = 1.f / l1;
    float* w0 = g_att + ((size_t)(b * Tt + tq0)) * Cc + h * Dd + d0;
    float* w1 = w0 + Cc;
#pragma unroll
    for (int i = 0; i < 4; i++) {
        float4 v;
        v.x = oa[i * 4 + 0] * inv0; v.y = oa[i * 4 + 1] * inv0;
        v.z = oa[i * 4 + 2] * inv0; v.w = oa[i * 4 + 3] * inv0;
        *(float4*)(w0 + i * 4) = v;
        v.x = ob[i * 4 + 0] * inv1; v.y = ob[i * 4 + 1] * inv1;
        v.z = ob[i * 4 + 2] * inv1; v.w = ob[i * 4 + 3] * inv1;
        *(float4*)(w1 + i * 4) = v;
    }
}

// ---------------------------------------------------------------------------
extern "C" void kernel_launch(void* const* d_in, const int* in_sizes, int n_in,
                              void* d_out, int out_size)
{
    const float* x      = (const float*)d_in[0];
    const float* w_attn = (const float*)d_in[1];
    const float* b_attn = (const float*)d_in[2];
    const float* w_proj = (const float*)d_in[3];
    const float* b_proj = (const float*)d_in[4];
    const float* cosp   = (const float*)d_in[5];
    const float* sinp   = (const float*)d_in[6];
    float* out = (float*)d_out;

    void *p_xh, *p_xl, *p_wh, *p_wl, *p_ph, *p_pl, *p_ah, *p_al, *p_att, *p_qkv;
    cudaGetSymbolAddress(&p_xh, g_xh);
    cudaGetSymbolAddress(&p_xl, g_xl);
    cudaGetSymbolAddress(&p_wh, g_wh);
    cudaGetSymbolAddress(&p_wl, g_wl);
    cudaGetSymbolAddress(&p_ph, g_ph);
    cudaGetSymbolAddress(&p_pl, g_pl);
    cudaGetSymbolAddress(&p_ah, g_ah);
    cudaGetSymbolAddress(&p_al, g_al);
    cudaGetSymbolAddress(&p_att, g_att);
    cudaGetSymbolAddress(&p_qkv, g_qkv);

    // 1) splits of x, w_attn, w_proj
    {
        int n4 = (Mtot * Cc) / 4;
        split_fp32_bf16<<<(n4 + 255) / 256, 256>>>(
            (const float4*)x, (__nv_bfloat162*)p_xh, (__nv_bfloat162*)p_xl, n4);
    }
    {
        int n4 = (3 * Cc * Cc) / 4;
        split_fp32_bf16<<<(n4 + 255) / 256, 256>>>(
            (const float4*)w_attn, (__nv_bfloat162*)p_wh, (__nv_bfloat162*)p_wl, n4);
    }
    {
        int n4 = (Cc * Cc) / 4;
        split_fp32_bf16<<<(n4 + 255) / 256, 256>>>(
            (const float4*)w_proj, (__nv_bfloat162*)p_ph, (__nv_bfloat162*)p_pl, n4);
    }

    // 2) QKV projection on tensor cores
    {
        dim3 grid((3 * Cc) / 128, Mtot / 128);
        gemm_bf16x3<<<grid, 256>>>(
            (const __nv_bfloat16*)p_xh, (const __nv_bfloat16*)p_xl,
            (const __nv_bfloat16*)p_wh, (const __nv_bfloat16*)p_wl,
            b_attn, (float*)p_qkv, 3 * Cc, Cc);
    }

    // 3) RoPE in place
    {
        int total = Bb * Tt * NHh * (Dd / 2);
        rope_kernel<<<total / 256, 256>>>(cosp, sinp);
    }

    // 4) causal flash attention -> g_att
    {
        dim3 grid(Tt / 128, Bb * NHh);
        flash_attn<<<grid, 256>>>();
    }

    // 5) split g_att
    {
        int n4 = (Mtot * Cc) / 4;
        split_fp32_bf16<<<(n4 + 255) / 256, 256>>>(
            (const float4*)p_att, (__nv_bfloat162*)p_ah, (__nv_bfloat162*)p_al, n4);
    }

    // 6) output projection
    {
        dim3 grid(Cc / 128, Mtot / 128);
        gemm_bf16x3<<<grid, 256>>>(
            (const __nv_bfloat16*)p_ah, (const __nv_bfloat16*)p_al,
            (const __nv_bfloat16*)p_ph, (const __nv_bfloat16*)p_pl,
            b_proj, out, Cc, Cc);
    }
}

// round 4
// speedup vs baseline: 4.6515x; 2.7265x over previous
#include <cuda_runtime.h>
#include <cuda_bf16.h>
#include <cstdint>

#define Bb 4
#define Tt 2048
#define Cc 1024
#define NHh 16
#define Dd 64
#define Mtot (Bb * Tt)   // 8192

// ------------------------- scratch (__device__ globals) --------------------
__device__ float g_qkv[(size_t)Bb * Tt * 3 * Cc];    // [B,T,3C] fp32
__device__ float g_att[(size_t)Bb * Tt * Cc];        // [B,T,C]  fp32
__device__ __nv_bfloat16 g_xh[(size_t)Mtot * Cc];
__device__ __nv_bfloat16 g_xl[(size_t)Mtot * Cc];
__device__ __nv_bfloat16 g_wh[(size_t)3 * Cc * Cc];
__device__ __nv_bfloat16 g_wl[(size_t)3 * Cc * Cc];
__device__ __nv_bfloat16 g_ph[(size_t)Cc * Cc];
__device__ __nv_bfloat16 g_pl[(size_t)Cc * Cc];
__device__ __nv_bfloat16 g_ah[(size_t)Mtot * Cc];
__device__ __nv_bfloat16 g_al[(size_t)Mtot * Cc];
// head-major [b*16+h][t][d] bf16 for attention
__device__ __nv_bfloat16 g_qh[(size_t)Mtot * Cc];
__device__ __nv_bfloat16 g_ql[(size_t)Mtot * Cc];
__device__ __nv_bfloat16 g_kh[(size_t)Mtot * Cc];
__device__ __nv_bfloat16 g_kl[(size_t)Mtot * Cc];
__device__ __nv_bfloat16 g_vh[(size_t)Mtot * Cc];
__device__ __nv_bfloat16 g_vl[(size_t)Mtot * Cc];

// ------------------------- helpers -----------------------------------------
__device__ __forceinline__ uint32_t smem_u32(const void* p) {
    uint32_t a;
    asm("{ .reg .u64 t; cvta.to.shared.u64 t, %1; cvt.u32.u64 %0, t; }"
        : "=r"(a) : "l"(p));
    return a;
}

__device__ __forceinline__ void ldmx4(uint32_t& r0, uint32_t& r1,
                                      uint32_t& r2, uint32_t& r3, uint32_t addr) {
    asm volatile("ldmatrix.sync.aligned.m8n8.x4.shared.b16 {%0,%1,%2,%3}, [%4];"
                 : "=r"(r0), "=r"(r1), "=r"(r2), "=r"(r3) : "r"(addr));
}

__device__ __forceinline__ void ldmx4t(uint32_t& r0, uint32_t& r1,
                                       uint32_t& r2, uint32_t& r3, uint32_t addr) {
    asm volatile("ldmatrix.sync.aligned.m8n8.x4.trans.shared.b16 {%0,%1,%2,%3}, [%4];"
                 : "=r"(r0), "=r"(r1), "=r"(r2), "=r"(r3) : "r"(addr));
}

__device__ __forceinline__ void mma16816(float* d, const uint32_t* a,
                                         uint32_t b0, uint32_t b1) {
    asm volatile(
        "mma.sync.aligned.m16n8k16.row.col.f32.bf16.bf16.f32 "
        "{%0,%1,%2,%3}, {%4,%5,%6,%7}, {%8,%9}, {%0,%1,%2,%3};"
        : "+f"(d[0]), "+f"(d[1]), "+f"(d[2]), "+f"(d[3])
        : "r"(a[0]), "r"(a[1]), "r"(a[2]), "r"(a[3]), "r"(b0), "r"(b1));
}

// pack two fp32 -> bf16x2 (lo = first arg, hi = second arg)
__device__ __forceinline__ uint32_t packbf(float lo, float hi) {
    uint32_t r;
    asm("cvt.rn.bf16x2.f32 %0, %1, %2;" : "=r"(r) : "f"(hi), "f"(lo));
    return r;
}

__device__ __forceinline__ void cp16(uint32_t dst, const void* src) {
    asm volatile("cp.async.cg.shared.global [%0], [%1], 16;" :: "r"(dst), "l"(src));
}
#define CP_COMMIT() asm volatile("cp.async.commit_group;" ::: "memory")
#define CP_WAIT0()  asm volatile("cp.async.wait_group 0;" ::: "memory")
#define CP_WAIT1()  asm volatile("cp.async.wait_group 1;" ::: "memory")

// ---------------------------------------------------------------------------
// bf16x3 GEMM via mma.sync (unchanged from R3 — known good)
// ---------------------------------------------------------------------------
#define SPAD 40
__global__ __launch_bounds__(256, 1)
void gemm_bf16x3(const __nv_bfloat16* __restrict__ Ah,
                 const __nv_bfloat16* __restrict__ Al,
                 const __nv_bfloat16* __restrict__ Bh,
                 const __nv_bfloat16* __restrict__ Bl,
                 const float* __restrict__ bias,
                 float* __restrict__ Cout, int N, int K)
{
    __shared__ __nv_bfloat16 sAh[128 * SPAD];
    __shared__ __nv_bfloat16 sAl[128 * SPAD];
    __shared__ __nv_bfloat16 sBh[128 * SPAD];
    __shared__ __nv_bfloat16 sBl[128 * SPAD];

    const int tid  = threadIdx.x;
    const int wid  = tid >> 5;
    const int lane = tid & 31;
    const int mw   = wid >> 2;
    const int nw   = wid & 3;
    const int m0   = blockIdx.y * 128;
    const int n0   = blockIdx.x * 128;

    const uint32_t uAh = smem_u32(sAh), uAl = smem_u32(sAl);
    const uint32_t uBh = smem_u32(sBh), uBl = smem_u32(sBl);

    const int lrow = lane & 15;
    const int lk   = (lane >> 4) * 8;
    uint32_t aoff[4], boff[2];
#pragma unroll
    for (int mt = 0; mt < 4; mt++)
        aoff[mt] = (uint32_t)(((mw * 64 + mt * 16 + lrow) * SPAD + lk) * 2);
#pragma unroll
    for (int ng = 0; ng < 2; ng++)
        boff[ng] = (uint32_t)(((nw * 32 + ng * 16 + lrow) * SPAD + lk) * 2);

    float acc[4][4][4];
#pragma unroll
    for (int i = 0; i < 4; i++)
#pragma unroll
        for (int j = 0; j < 4; j++)
#pragma unroll
            for (int e = 0; e < 4; e++) acc[i][j][e] = 0.f;

    const int kq = K >> 3;
    const int nk = K >> 5;

    const int r0i = tid >> 2, c0i = tid & 3;
    const int r1i = (tid + 256) >> 2, c1i = tid & 3;

    for (int kc = 0; kc < nk; kc++) {
        __syncthreads();
        {
            const size_t ab = ((size_t)m0) * kq + kc * 4;
            const size_t bb = ((size_t)n0) * kq + kc * 4;
            uint4* s;
            s = (uint4*)sAh;
            s[r0i * 5 + c0i] = ((const uint4*)Ah)[ab + (size_t)r0i * kq + c0i];
            s[r1i * 5 + c1i] = ((const uint4*)Ah)[ab + (size_t)r1i * kq + c1i];
            s = (uint4*)sAl;
            s[r0i * 5 + c0i] = ((const uint4*)Al)[ab + (size_t)r0i * kq + c0i];
            s[r1i * 5 + c1i] = ((const uint4*)Al)[ab + (size_t)r1i * kq + c1i];
            s = (uint4*)sBh;
            s[r0i * 5 + c0i] = ((const uint4*)Bh)[bb + (size_t)r0i * kq + c0i];
            s[r1i * 5 + c1i] = ((const uint4*)Bh)[bb + (size_t)r1i * kq + c1i];
            s = (uint4*)sBl;
            s[r0i * 5 + c0i] = ((const uint4*)Bl)[bb + (size_t)r0i * kq + c0i];
            s[r1i * 5 + c1i] = ((const uint4*)Bl)[bb + (size_t)r1i * kq + c1i];
        }
        __syncthreads();

#pragma unroll
        for (int ks = 0; ks < 2; ks++) {
            const uint32_t kb = ks * 32;
            uint32_t ah[4][4], al[4][4];
#pragma unroll
            for (int mt = 0; mt < 4; mt++) {
                ldmx4(ah[mt][0], ah[mt][1], ah[mt][2], ah[mt][3], uAh + aoff[mt] + kb);
                ldmx4(al[mt][0], al[mt][1], al[mt][2], al[mt][3], uAl + aoff[mt] + kb);
            }
            uint32_t bh[2][4], bl[2][4];
#pragma unroll
            for (int ng = 0; ng < 2; ng++) {
                ldmx4(bh[ng][0], bh[ng][1], bh[ng][2], bh[ng][3], uBh + boff[ng] + kb);
                ldmx4(bl[ng][0], bl[ng][1], bl[ng][2], bl[ng][3], uBl + boff[ng] + kb);
            }
#pragma unroll
            for (int mt = 0; mt < 4; mt++) {
#pragma unroll
                for (int ng = 0; ng < 2; ng++) {
#pragma unroll
                    for (int sub = 0; sub < 2; sub++) {
                        const int nt = ng * 2 + sub;
                        const uint32_t bh0 = bh[ng][sub], bh1 = bh[ng][sub + 2];
                        const uint32_t bl0 = bl[ng][sub], bl1 = bl[ng][sub + 2];
                        mma16816(acc[mt][nt], ah[mt], bh0, bh1);
                        mma16816(acc[mt][nt], ah[mt], bl0, bl1);
                        mma16816(acc[mt][nt], al[mt], bh0, bh1);
                    }
                }
            }
        }
    }

    const int erow = lane >> 2;
    const int ecol = (lane & 3) * 2;
#pragma unroll
    for (int mt = 0; mt < 4; mt++) {
#pragma unroll
        for (int nt = 0; nt < 4; nt++) {
            const int row = m0 + mw * 64 + mt * 16 + erow;
            const int col = n0 + nw * 32 + nt * 8 + ecol;
            const float b0 = bias[col], b1 = bias[col + 1];
            float2 v;
            v.x = acc[mt][nt][0] + b0;
            v.y = acc[mt][nt][1] + b1;
            *(float2*)(Cout + (size_t)row * N + col) = v;
            v.x = acc[mt][nt][2] + b0;
            v.y = acc[mt][nt][3] + b1;
            *(float2*)(Cout + (size_t)(row + 8) * N + col) = v;
        }
    }
}

// ---------------------------------------------------------------------------
// fp32 -> (hi,lo) bf16 split, vectorized by 4
// ---------------------------------------------------------------------------
__global__ void split_fp32_bf16(const float4* __restrict__ src,
                                __nv_bfloat162* __restrict__ hi,
                                __nv_bfloat162* __restrict__ lo, int n4)
{
    int i = blockIdx.x * 256 + threadIdx.x;
    if (i >= n4) return;
    float4 v = src[i];
    __nv_bfloat16 hx = __float2bfloat16(v.x);
    __nv_bfloat16 hy = __float2bfloat16(v.y);
    __nv_bfloat16 hz = __float2bfloat16(v.z);
    __nv_bfloat16 hw = __float2bfloat16(v.w);
    __nv_bfloat16 lx = __float2bfloat16(v.x - __bfloat162float(hx));
    __nv_bfloat16 ly = __float2bfloat16(v.y - __bfloat162float(hy));
    __nv_bfloat16 lz = __float2bfloat16(v.z - __bfloat162float(hz));
    __nv_bfloat16 lw = __float2bfloat16(v.w - __bfloat162float(hw));
    __nv_bfloat162 a;
    a.x = hx; a.y = hy; hi[2 * i] = a;
    a.x = hz; a.y = hw; hi[2 * i + 1] = a;
    a.x = lx; a.y = ly; lo[2 * i] = a;
    a.x = lz; a.y = lw; lo[2 * i + 1] = a;
}

// ---------------------------------------------------------------------------
// Fused RoPE + head-major relayout + hi/lo bf16 split of q,k,v.
// Thread handles (b,t,h, d-slice of 4 within [0,32)) -> 8 q, 8 k, 8 v elems.
// q is pre-scaled by 1/sqrt(D).
// ---------------------------------------------------------------------------
__device__ __forceinline__ void split_store4(__nv_bfloat16* ph, __nv_bfloat16* pl,
                                             float a, float b, float c, float d)
{
    __nv_bfloat16 h0 = __float2bfloat16(a), h1 = __float2bfloat16(b);
    __nv_bfloat16 h2 = __float2bfloat16(c), h3 = __float2bfloat16(d);
    __nv_bfloat162 v;
    v.x = h0; v.y = h1; *(__nv_bfloat162*)ph = v;
    v.x = h2; v.y = h3; *(__nv_bfloat162*)(ph + 2) = v;
    v.x = __float2bfloat16(a - __bfloat162float(h0));
    v.y = __float2bfloat16(b - __bfloat162float(h1));
    *(__nv_bfloat162*)pl = v;
    v.x = __float2bfloat16(c - __bfloat162float(h2));
    v.y = __float2bfloat16(d - __bfloat162float(h3));
    *(__nv_bfloat162*)(pl + 2) = v;
}

__global__ void rope_split(const float* __restrict__ cosp,
                           const float* __restrict__ sinp)
{
    int idx = blockIdx.x * 256 + threadIdx.x;   // B*T*NH*8 total
    int ds = idx & 7;
    int h  = (idx >> 3) & 15;
    int t  = (idx >> 7) & 2047;
    int b  = idx >> 18;
    int d0 = ds * 4;

    const float* base = g_qkv + ((size_t)(b * Tt + t)) * (3 * Cc) + h * Dd;
    float4 q1 = *(const float4*)(base + d0);
    float4 q2 = *(const float4*)(base + d0 + 32);
    float4 k1 = *(const float4*)(base + Cc + d0);
    float4 k2 = *(const float4*)(base + Cc + d0 + 32);
    float4 v1 = *(const float4*)(base + 2 * Cc + d0);
    float4 v2 = *(const float4*)(base + 2 * Cc + d0 + 32);
    float4 cw = *(const float4*)(cosp + t * Dd + d0);
    float4 sw = *(const float4*)(sinp + t * Dd + d0);

    const float sc = 0.125f;
    // rotated q (scaled)
    float qa0 = (q1.x * cw.x - q2.x * sw.x) * sc;
    float qa1 = (q1.y * cw.y - q2.y * sw.y) * sc;
    float qa2 = (q1.z * cw.z - q2.z * sw.z) * sc;
    float qa3 = (q1.w * cw.w - q2.w * sw.w) * sc;
    float qb0 = (q2.x * cw.x + q1.x * sw.x) * sc;
    float qb1 = (q2.y * cw.y + q1.y * sw.y) * sc;
    float qb2 = (q2.z * cw.z + q1.z * sw.z) * sc;
    float qb3 = (q2.w * cw.w + q1.w * sw.w) * sc;
    // rotated k
    float ka0 = k1.x * cw.x - k2.x * sw.x;
    float ka1 = k1.y * cw.y - k2.y * sw.y;
    float ka2 = k1.z * cw.z - k2.z * sw.z;
    float ka3 = k1.w * cw.w - k2.w * sw.w;
    float kb0 = k2.x * cw.x + k1.x * sw.x;
    float kb1 = k2.y * cw.y + k1.y * sw.y;
    float kb2 = k2.z * cw.z + k1.z * sw.z;
    float kb3 = k2.w * cw.w + k1.w * sw.w;

    size_t ob = (((size_t)(b * NHh + h)) * Tt + t) * Dd;
    split_store4(g_qh + ob + d0,      g_ql + ob + d0,      qa0, qa1, qa2, qa3);
    split_store4(g_qh + ob + d0 + 32, g_ql + ob + d0 + 32, qb0, qb1, qb2, qb3);
    split_store4(g_kh + ob + d0,      g_kl + ob + d0,      ka0, ka1, ka2, ka3);
    split_store4(g_kh + ob + d0 + 32, g_kl + ob + d0 + 32, kb0, kb1, kb2, kb3);
    split_store4(g_vh + ob + d0,      g_vl + ob + d0,      v1.x, v1.y, v1.z, v1.w);
    split_store4(g_vh + ob + d0 + 32, g_vl + ob + d0 + 32, v2.x, v2.y, v2.z, v2.w);
}

// ---------------------------------------------------------------------------
// Flash attention on mma.sync (bf16 hi/lo split, fp32 softmax).
// Grid (32, 64): CTA = 64 q rows of one (b,h); 4 warps x 16 rows.
// K/V tiles (64 keys) double-buffered via cp.async.
// ---------------------------------------------------------------------------
#define SROW 72
#define TILE_B 9216u   // 64*72*2 bytes per matrix buffer

__global__ __launch_bounds__(128, 1) void flash_mma()
{
    extern __shared__ char fsm[];
    const uint32_t sb = smem_u32(fsm);

    const int bh = blockIdx.y;
    const int qt = (gridDim.x - 1) - blockIdx.x;
    const int q0 = qt * 64;
    const int tid = threadIdx.x, wid = tid >> 5, lane = tid & 31;

    const size_t hb = (size_t)bh * Tt * Dd;
    const __nv_bfloat16* Qh = g_qh + hb + (size_t)q0 * Dd;
    const __nv_bfloat16* Ql = g_ql + hb + (size_t)q0 * Dd;
    const __nv_bfloat16* Kh = g_kh + hb;
    const __nv_bfloat16* Kl = g_kl + hb;
    const __nv_bfloat16* Vh = g_vh + hb;
    const __nv_bfloat16* Vl = g_vl + hb;

    // smem buffer offsets: [buf][mat] mat: 0=Kh 1=Kl 2=Vh 3=Vl
    // Q staged in buf1 slots 0 (hi) and 1 (lo)
    auto soff = [&](int buf, int mat) -> uint32_t {
        return sb + (uint32_t)(buf * 4 + mat) * TILE_B;
    };

    // ---- prologue: stage Q into buf1 slots 0,1; load tile 0 into buf0 ----
    {
        // Q: 2 matrices x 64 rows x 64 bf16
#pragma unroll
        for (int i = 0; i < 4; i++) {
            int lin = tid + i * 128;
            int r = lin >> 3, c = (lin & 7) * 8;
            uint32_t so = (uint32_t)(r * SROW + c) * 2;
            cp16(soff(1, 0) + so, Qh + (size_t)r * Dd + c);
            cp16(soff(1, 1) + so, Ql + (size_t)r * Dd + c);
        }
        CP_COMMIT();
#pragma unroll
        for (int i = 0; i < 4; i++) {
            int lin = tid + i * 128;
            int r = lin >> 3, c = (lin & 7) * 8;
            uint32_t so = (uint32_t)(r * SROW + c) * 2;
            cp16(soff(0, 0) + so, Kh + (size_t)r * Dd + c);
            cp16(soff(0, 1) + so, Kl + (size_t)r * Dd + c);
            cp16(soff(0, 2) + so, Vh + (size_t)r * Dd + c);
            cp16(soff(0, 3) + so, Vl + (size_t)r * Dd + c);
        }
        CP_COMMIT();
        CP_WAIT0();
        __syncthreads();
    }

    // ---- Q fragments (registers) ----
    uint32_t QHf[4][4], QLf[4][4];
    {
        const int row = wid * 16 + (lane & 15);
        const int ck  = (lane >> 4) * 8;
#pragma unroll
        for (int kk = 0; kk < 4; kk++) {
            uint32_t ao = (uint32_t)(row * SROW + kk * 16 + ck) * 2;
            ldmx4(QHf[kk][0], QHf[kk][1], QHf[kk][2], QHf[kk][3], soff(1, 0) + ao);
            ldmx4(QLf[kk][0], QLf[kk][1], QLf[kk][2], QLf[kk][3], soff(1, 1) + ao);
        }
    }

    float O[8][4];
#pragma unroll
    for (int i = 0; i < 8; i++)
#pragma unroll
        for (int e = 0; e < 4; e++) O[i][e] = 0.f;
    float m0 = -1e30f, m1 = -1e30f, l0 = 0.f, l1 = 0.f;

    // per-lane ldmatrix helpers
    const int klrow = lane & 15;
    const int klk   = (lane >> 4) * 8;
    const int vg    = lane >> 3;
    const int vrow_in = (vg & 1) * 8 + (lane & 7);
    const int vcol_of = (vg >> 1) * 8;

    for (int jt = 0; jt <= qt; jt++) {
        const int buf = jt & 1;
        __syncthreads();   // (A) prev compute done; Q-frag reads done (jt=0)
        if (jt < qt) {
            const int j1 = (jt + 1) * 64;
#pragma unroll
            for (int i = 0; i < 4; i++) {
                int lin = tid + i * 128;
                int r = lin >> 3, c = (lin & 7) * 8;
                uint32_t so = (uint32_t)(r * SROW + c) * 2;
                size_t gi = (size_t)(j1 + r) * Dd + c;
                cp16(soff(buf ^ 1, 0) + so, Kh + gi);
                cp16(soff(buf ^ 1, 1) + so, Kl + gi);
                cp16(soff(buf ^ 1, 2) + so, Vh + gi);
                cp16(soff(buf ^ 1, 3) + so, Vl + gi);
            }
            CP_COMMIT();
            CP_WAIT1();
        } else {
            CP_WAIT0();
        }
        __syncthreads();   // (B) tile jt visible to all

        // ---- S = Q K^T (bf16x3) ----
        float S[8][4];
#pragma unroll
        for (int i = 0; i < 8; i++)
#pragma unroll
            for (int e = 0; e < 4; e++) S[i][e] = 0.f;

#pragma unroll
        for (int jg = 0; jg < 4; jg++) {
#pragma unroll
            for (int kk = 0; kk < 4; kk++) {
                uint32_t ao = (uint32_t)((jg * 16 + klrow) * SROW + kk * 16 + klk) * 2;
                uint32_t kh0, kh1, kh2, kh3, kl0, kl1, kl2, kl3;
                ldmx4(kh0, kh1, kh2, kh3, soff(buf, 0) + ao);
                ldmx4(kl0, kl1, kl2, kl3, soff(buf, 1) + ao);
                mma16816(S[jg * 2 + 0], QHf[kk], kh0, kh2);
                mma16816(S[jg * 2 + 0], QLf[kk], kh0, kh2);
                mma16816(S[jg * 2 + 0], QHf[kk], kl0, kl2);
                mma16816(S[jg * 2 + 1], QHf[kk], kh1, kh3);
                mma16816(S[jg * 2 + 1], QLf[kk], kh1, kh3);
                mma16816(S[jg * 2 + 1], QHf[kk], kl1, kl3);
            }
        }

        // ---- causal mask on diagonal tile ----
        if (jt == qt) {
            const int r0l = wid * 16 + (lane >> 2);
            const int cb  = (lane & 3) * 2;
#pragma unroll
            for (int nf = 0; nf < 8; nf++) {
                int c0 = nf * 8 + cb;
                if (c0     > r0l)     S[nf][0] = -1e30f;
                if (c0 + 1 > r0l)     S[nf][1] = -1e30f;
                if (c0     > r0l + 8) S[nf][2] = -1e30f;
                if (c0 + 1 > r0l + 8) S[nf][3] = -1e30f;
            }
        }

        // ---- online softmax ----
        float tm0 = -1e30f, tm1 = -1e30f;
#pragma unroll
        for (int nf = 0; nf < 8; nf++) {
            tm0 = fmaxf(tm0, fmaxf(S[nf][0], S[nf][1]));
            tm1 = fmaxf(tm1, fmaxf(S[nf][2], S[nf][3]));
        }
        tm0 = fmaxf(tm0, __shfl_xor_sync(0xffffffff, tm0, 1));
        tm0 = fmaxf(tm0, __shfl_xor_sync(0xffffffff, tm0, 2));
        tm1 = fmaxf(tm1, __shfl_xor_sync(0xffffffff, tm1, 1));
        tm1 = fmaxf(tm1, __shfl_xor_sync(0xffffffff, tm1, 2));

        float m0n = fmaxf(m0, tm0), m1n = fmaxf(m1, tm1);
        float sc0 = __expf(m0 - m0n), sc1 = __expf(m1 - m1n);
        l0 *= sc0; l1 *= sc1;
#pragma unroll
        for (int i = 0; i < 8; i++) {
            O[i][0] *= sc0; O[i][1] *= sc0;
            O[i][2] *= sc1; O[i][3] *= sc1;
        }
#pragma unroll
        for (int nf = 0; nf < 8; nf++) {
            S[nf][0] = __expf(S[nf][0] - m0n);
            S[nf][1] = __expf(S[nf][1] - m0n);
            S[nf][2] = __expf(S[nf][2] - m1n);
            S[nf][3] = __expf(S[nf][3] - m1n);
            l0 += S[nf][0] + S[nf][1];
            l1 += S[nf][2] + S[nf][3];
        }
        m0 = m0n; m1 = m1n;

        // ---- O += P V (bf16x3) ----
#pragma unroll
        for (int kk = 0; kk < 4; kk++) {
            const float* s0 = S[2 * kk];
            const float* s1 = S[2 * kk + 1];
            uint32_t PH[4], PL[4];
            PH[0] = packbf(s0[0], s0[1]);
            PH[1] = packbf(s0[2], s0[3]);
            PH[2] = packbf(s1[0], s1[1]);
            PH[3] = packbf(s1[2], s1[3]);
#pragma unroll
            for (int e = 0; e < 4; e++) {
                const float* sv = (e < 2) ? s0 : s1;
                float c0 = sv[(e & 1) * 2], c1 = sv[(e & 1) * 2 + 1];
                float f0 = __uint_as_float(PH[e] << 16);
                float f1 = __uint_as_float(PH[e] & 0xffff0000u);
                PL[e] = packbf(c0 - f0, c1 - f1);
            }
#pragma unroll
            for (int dc = 0; dc < 4; dc++) {
                uint32_t vo = (uint32_t)((kk * 16 + vrow_in) * SROW + dc * 16 + vcol_of) * 2;
                uint32_t vh0, vh1, vh2, vh3, vl0, vl1, vl2, vl3;
                ldmx4t(vh0, vh1, vh2, vh3, soff(buf, 2) + vo);
                ldmx4t(vl0, vl1, vl2, vl3, soff(buf, 3) + vo);
                mma16816(O[dc * 2 + 0], PH, vh0, vh1);
                mma16816(O[dc * 2 + 0], PL, vh0, vh1);
                mma16816(O[dc * 2 + 0], PH, vl0, vl1);
                mma16816(O[dc * 2 + 1], PH, vh2, vh3);
                mma16816(O[dc * 2 + 1], PL, vh2, vh3);
                mma16816(O[dc * 2 + 1], PH, vl2, vl3);
            }
        }
    }

    // ---- finalize ----
    l0 += __shfl_xor_sync(0xffffffff, l0, 1);
    l0 += __shfl_xor_sync(0xffffffff, l0, 2);
    l1 += __shfl_xor_sync(0xffffffff, l1, 1);
    l1 += __shfl_xor_sync(0xffffffff, l1, 2);
    const float i0 = 1.f / l0, i1 = 1.f / l1;

    const int b = bh >> 4, h = bh & 15;
    const int t0 = q0 + wid * 16 + (lane >> 2);
    const int t1 = t0 + 8;
    float* o0 = g_att + ((size_t)(b * Tt + t0)) * Cc + h * Dd + (lane & 3) * 2;
    float* o1 = g_att + ((size_t)(b * Tt + t1)) * Cc + h * Dd + (lane & 3) * 2;
#pragma unroll
    for (int nf = 0; nf < 8; nf++) {
        float2 v;
        v.x = O[nf][0] * i0; v.y = O[nf][1] * i0;
        *(float2*)(o0 + nf * 8) = v;
        v.x = O[nf][2] * i1; v.y = O[nf][3] * i1;
        *(float2*)(o1 + nf * 8) = v;
    }
}

// ---------------------------------------------------------------------------
extern "C" void kernel_launch(void* const* d_in, const int* in_sizes, int n_in,
                              void* d_out, int out_size)
{
    const float* x      = (const float*)d_in[0];
    const float* w_attn = (const float*)d_in[1];
    const float* b_attn = (const float*)d_in[2];
    const float* w_proj = (const float*)d_in[3];
    const float* b_proj = (const float*)d_in[4];
    const float* cosp   = (const float*)d_in[5];
    const float* sinp   = (const float*)d_in[6];
    float* out = (float*)d_out;

    void *p_xh, *p_xl, *p_wh, *p_wl, *p_ph, *p_pl, *p_ah, *p_al, *p_att, *p_qkv;
    cudaGetSymbolAddress(&p_xh, g_xh);
    cudaGetSymbolAddress(&p_xl, g_xl);
    cudaGetSymbolAddress(&p_wh, g_wh);
    cudaGetSymbolAddress(&p_wl, g_wl);
    cudaGetSymbolAddress(&p_ph, g_ph);
    cudaGetSymbolAddress(&p_pl, g_pl);
    cudaGetSymbolAddress(&p_ah, g_ah);
    cudaGetSymbolAddress(&p_al, g_al);
    cudaGetSymbolAddress(&p_att, g_att);
    cudaGetSymbolAddress(&p_qkv, g_qkv);

    static bool once = false;
    if (!once) {
        cudaFuncSetAttribute(flash_mma,
                             cudaFuncAttributeMaxDynamicSharedMemorySize, 8 * TILE_B);
        once = true;
    }

    // 1) splits of x, w_attn, w_proj
    {
        int n4 = (Mtot * Cc) / 4;
        split_fp32_bf16<<<(n4 + 255) / 256, 256>>>(
            (const float4*)x, (__nv_bfloat162*)p_xh, (__nv_bfloat162*)p_xl, n4);
    }
    {
        int n4 = (3 * Cc * Cc) / 4;
        split_fp32_bf16<<<(n4 + 255) / 256, 256>>>(
            (const float4*)w_attn, (__nv_bfloat162*)p_wh, (__nv_bfloat162*)p_wl, n4);
    }
    {
        int n4 = (Cc * Cc) / 4;
        split_fp32_bf16<<<(n4 + 255) / 256, 256>>>(
            (const float4*)w_proj, (__nv_bfloat162*)p_ph, (__nv_bfloat162*)p_pl, n4);
    }

    // 2) QKV projection on tensor cores -> g_qkv fp32
    {
        dim3 grid((3 * Cc) / 128, Mtot / 128);
        gemm_bf16x3<<<grid, 256>>>(
            (const __nv_bfloat16*)p_xh, (const __nv_bfloat16*)p_xl,
            (const __nv_bfloat16*)p_wh, (const __nv_bfloat16*)p_wl,
            b_attn, (float*)p_qkv, 3 * Cc, Cc);
    }

    // 3) fused RoPE + relayout + bf16 split of q,k,v
    {
        int total = Bb * Tt * NHh * 8;   // 1,048,576
        rope_split<<<total / 256, 256>>>(cosp, sinp);
    }

    // 4) flash attention on tensor cores -> g_att fp32
    {
        dim3 grid(Tt / 64, Bb * NHh);
        flash_mma<<<grid, 128, 8 * TILE_B>>>();
    }

    // 5) split g_att
    {
        int n4 = (Mtot * Cc) / 4;
        split_fp32_bf16<<<(n4 + 255) / 256, 256>>>(
            (const float4*)p_att, (__nv_bfloat162*)p_ah, (__nv_bfloat162*)p_al, n4);
    }

    // 6) output projection
    {
        dim3 grid(Cc / 128, Mtot / 128);
        gemm_bf16x3<<<grid, 256>>>(
            (const __nv_bfloat16*)p_ah, (const __nv_bfloat16*)p_al,
            (const __nv_bfloat16*)p_ph, (const __nv_bfloat16*)p_pl,
            b_proj, out, Cc, Cc);
    }
}

// round 5
// speedup vs baseline: 5.2176x; 1.1217x over previous
#include <cuda_runtime.h>
#include <cuda_bf16.h>
#include <cstdint>

#define Bb 4
#define Tt 2048
#define Cc 1024
#define NHh 16
#define Dd 64
#define Mtot (Bb * Tt)   // 8192

// ------------------------- scratch (__device__ globals) --------------------
__device__ float g_qkv[(size_t)Bb * Tt * 3 * Cc];    // [B,T,3C] fp32
__device__ __nv_bfloat16 g_xh[(size_t)Mtot * Cc];
__device__ __nv_bfloat16 g_xl[(size_t)Mtot * Cc];
__device__ __nv_bfloat16 g_wh[(size_t)3 * Cc * Cc];
__device__ __nv_bfloat16 g_wl[(size_t)3 * Cc * Cc];
__device__ __nv_bfloat16 g_ph[(size_t)Cc * Cc];
__device__ __nv_bfloat16 g_pl[(size_t)Cc * Cc];
__device__ __nv_bfloat16 g_ah[(size_t)Mtot * Cc];
__device__ __nv_bfloat16 g_al[(size_t)Mtot * Cc];
// head-major [b*16+h][t][d] bf16 for attention
__device__ __nv_bfloat16 g_qh[(size_t)Mtot * Cc];
__device__ __nv_bfloat16 g_ql[(size_t)Mtot * Cc];
__device__ __nv_bfloat16 g_kh[(size_t)Mtot * Cc];
__device__ __nv_bfloat16 g_kl[(size_t)Mtot * Cc];
__device__ __nv_bfloat16 g_vh[(size_t)Mtot * Cc];
__device__ __nv_bfloat16 g_vl[(size_t)Mtot * Cc];

// ------------------------- helpers -----------------------------------------
__device__ __forceinline__ uint32_t smem_u32(const void* p) {
    uint32_t a;
    asm("{ .reg .u64 t; cvta.to.shared.u64 t, %1; cvt.u32.u64 %0, t; }"
        : "=r"(a) : "l"(p));
    return a;
}

__device__ __forceinline__ void ldmx4(uint32_t& r0, uint32_t& r1,
                                      uint32_t& r2, uint32_t& r3, uint32_t addr) {
    asm volatile("ldmatrix.sync.aligned.m8n8.x4.shared.b16 {%0,%1,%2,%3}, [%4];"
                 : "=r"(r0), "=r"(r1), "=r"(r2), "=r"(r3) : "r"(addr));
}

__device__ __forceinline__ void ldmx4t(uint32_t& r0, uint32_t& r1,
                                       uint32_t& r2, uint32_t& r3, uint32_t addr) {
    asm volatile("ldmatrix.sync.aligned.m8n8.x4.trans.shared.b16 {%0,%1,%2,%3}, [%4];"
                 : "=r"(r0), "=r"(r1), "=r"(r2), "=r"(r3) : "r"(addr));
}

__device__ __forceinline__ void mma16816(float* d, const uint32_t* a,
                                         uint32_t b0, uint32_t b1) {
    asm volatile(
        "mma.sync.aligned.m16n8k16.row.col.f32.bf16.bf16.f32 "
        "{%0,%1,%2,%3}, {%4,%5,%6,%7}, {%8,%9}, {%0,%1,%2,%3};"
        : "+f"(d[0]), "+f"(d[1]), "+f"(d[2]), "+f"(d[3])
        : "r"(a[0]), "r"(a[1]), "r"(a[2]), "r"(a[3]), "r"(b0), "r"(b1));
}

__device__ __forceinline__ uint32_t packbf(float lo, float hi) {
    uint32_t r;
    asm("cvt.rn.bf16x2.f32 %0, %1, %2;" : "=r"(r) : "f"(hi), "f"(lo));
    return r;
}

__device__ __forceinline__ void cp16(uint32_t dst, const void* src) {
    asm volatile("cp.async.cg.shared.global [%0], [%1], 16;" :: "r"(dst), "l"(src));
}
#define CP_COMMIT() asm volatile("cp.async.commit_group;" ::: "memory")
#define CP_WAIT0()  asm volatile("cp.async.wait_group 0;" ::: "memory")
#define CP_WAIT1()  asm volatile("cp.async.wait_group 1;" ::: "memory")

// ---------------------------------------------------------------------------
// bf16x3 GEMM via mma.sync, cp.async 2-stage pipelined.
// C[M,N] = (Ah+Al)[M,K] @ (Bh+Bl)[N,K]^T + bias[N]
// CTA tile 128x128, BK=32, 8 warps (2m x 4n), warp tile 64x32.
// Dynamic smem: 2 stages x 4 matrices x 128 rows x 40 bf16 = 81920 B.
// ---------------------------------------------------------------------------
#define SPAD 40
#define GMAT (128 * SPAD * 2u)   // bytes per matrix per stage (10240)

__global__ __launch_bounds__(256, 1)
void gemm_bf16x3(const __nv_bfloat16* __restrict__ Ah,
                 const __nv_bfloat16* __restrict__ Al,
                 const __nv_bfloat16* __restrict__ Bh,
                 const __nv_bfloat16* __restrict__ Bl,
                 const float* __restrict__ bias,
                 float* __restrict__ Cout, int N, int K)
{
    extern __shared__ char gsm[];
    const uint32_t sb = smem_u32(gsm);

    const int tid  = threadIdx.x;
    const int wid  = tid >> 5;
    const int lane = tid & 31;
    const int mw   = wid >> 2;
    const int nw   = wid & 3;
    const int m0   = blockIdx.y * 128;
    const int n0   = blockIdx.x * 128;

    // stage/matrix smem base (mat: 0=Ah 1=Al 2=Bh 3=Bl)
    auto stoff = [&](int s, int m) -> uint32_t {
        return sb + (uint32_t)(s * 4 + m) * GMAT;
    };

    // loader coords: each matrix = 128 rows x 64 B = 512 x 16B chunks, 2/thread
    const int r0i = tid >> 2, ci = tid & 3;
    const int r1i = r0i + 64;
    const uint32_t so0 = (uint32_t)(r0i * (SPAD * 2) + ci * 16);
    const uint32_t so1 = (uint32_t)(r1i * (SPAD * 2) + ci * 16);
    const int kq = K >> 3;   // row stride in uint4
    const int nk = K >> 5;   // number of 32-wide chunks

    auto load_stage = [&](int s, int kc) {
        const size_t a0 = (size_t)(m0 + r0i) * kq + kc * 4 + ci;
        const size_t a1 = (size_t)(m0 + r1i) * kq + kc * 4 + ci;
        const size_t b0 = (size_t)(n0 + r0i) * kq + kc * 4 + ci;
        const size_t b1 = (size_t)(n0 + r1i) * kq + kc * 4 + ci;
        cp16(stoff(s, 0) + so0, (const uint4*)Ah + a0);
        cp16(stoff(s, 0) + so1, (const uint4*)Ah + a1);
        cp16(stoff(s, 1) + so0, (const uint4*)Al + a0);
        cp16(stoff(s, 1) + so1, (const uint4*)Al + a1);
        cp16(stoff(s, 2) + so0, (const uint4*)Bh + b0);
        cp16(stoff(s, 2) + so1, (const uint4*)Bh + b1);
        cp16(stoff(s, 3) + so0, (const uint4*)Bl + b0);
        cp16(stoff(s, 3) + so1, (const uint4*)Bl + b1);
    };

    // per-lane ldmatrix offsets (matrix-local bytes)
    const int lrow = lane & 15;
    const int lk   = (lane >> 4) * 8;
    uint32_t aoff[4], boff[2];
#pragma unroll
    for (int mt = 0; mt < 4; mt++)
        aoff[mt] = (uint32_t)(((mw * 64 + mt * 16 + lrow) * SPAD + lk) * 2);
#pragma unroll
    for (int ng = 0; ng < 2; ng++)
        boff[ng] = (uint32_t)(((nw * 32 + ng * 16 + lrow) * SPAD + lk) * 2);

    float acc[4][4][4];
#pragma unroll
    for (int i = 0; i < 4; i++)
#pragma unroll
        for (int j = 0; j < 4; j++)
#pragma unroll
            for (int e = 0; e < 4; e++) acc[i][j][e] = 0.f;

    load_stage(0, 0);
    CP_COMMIT();

    for (int kc = 0; kc < nk; kc++) {
        const int s = kc & 1;
        if (kc + 1 < nk) {
            load_stage(s ^ 1, kc + 1);
            CP_COMMIT();
            CP_WAIT1();
        } else {
            CP_WAIT0();
        }
        __syncthreads();

        const uint32_t uAh = stoff(s, 0), uAl = stoff(s, 1);
        const uint32_t uBh = stoff(s, 2), uBl = stoff(s, 3);
#pragma unroll
        for (int ks = 0; ks < 2; ks++) {
            const uint32_t kb = ks * 32;
            uint32_t ah[4][4], al[4][4];
#pragma unroll
            for (int mt = 0; mt < 4; mt++) {
                ldmx4(ah[mt][0], ah[mt][1], ah[mt][2], ah[mt][3], uAh + aoff[mt] + kb);
                ldmx4(al[mt][0], al[mt][1], al[mt][2], al[mt][3], uAl + aoff[mt] + kb);
            }
            uint32_t bh[2][4], bl[2][4];
#pragma unroll
            for (int ng = 0; ng < 2; ng++) {
                ldmx4(bh[ng][0], bh[ng][1], bh[ng][2], bh[ng][3], uBh + boff[ng] + kb);
                ldmx4(bl[ng][0], bl[ng][1], bl[ng][2], bl[ng][3], uBl + boff[ng] + kb);
            }
#pragma unroll
            for (int mt = 0; mt < 4; mt++) {
#pragma unroll
                for (int ng = 0; ng < 2; ng++) {
#pragma unroll
                    for (int sub = 0; sub < 2; sub++) {
                        const int nt = ng * 2 + sub;
                        const uint32_t bh0 = bh[ng][sub], bh1 = bh[ng][sub + 2];
                        const uint32_t bl0 = bl[ng][sub], bl1 = bl[ng][sub + 2];
                        mma16816(acc[mt][nt], ah[mt], bh0, bh1);
                        mma16816(acc[mt][nt], ah[mt], bl0, bl1);
                        mma16816(acc[mt][nt], al[mt], bh0, bh1);
                    }
                }
            }
        }
        __syncthreads();
    }

    const int erow = lane >> 2;
    const int ecol = (lane & 3) * 2;
#pragma unroll
    for (int mt = 0; mt < 4; mt++) {
#pragma unroll
        for (int nt = 0; nt < 4; nt++) {
            const int row = m0 + mw * 64 + mt * 16 + erow;
            const int col = n0 + nw * 32 + nt * 8 + ecol;
            const float b0 = bias[col], b1 = bias[col + 1];
            float2 v;
            v.x = acc[mt][nt][0] + b0;
            v.y = acc[mt][nt][1] + b1;
            *(float2*)(Cout + (size_t)row * N + col) = v;
            v.x = acc[mt][nt][2] + b0;
            v.y = acc[mt][nt][3] + b1;
            *(float2*)(Cout + (size_t)(row + 8) * N + col) = v;
        }
    }
}
#define GEMM_SMEM (2u * 4u * GMAT)   // 81920

// ---------------------------------------------------------------------------
// fp32 -> (hi,lo) bf16 split, vectorized by 4
// ---------------------------------------------------------------------------
__global__ void split_fp32_bf16(const float4* __restrict__ src,
                                __nv_bfloat162* __restrict__ hi,
                                __nv_bfloat162* __restrict__ lo, int n4)
{
    int i = blockIdx.x * 256 + threadIdx.x;
    if (i >= n4) return;
    float4 v = src[i];
    __nv_bfloat16 hx = __float2bfloat16(v.x);
    __nv_bfloat16 hy = __float2bfloat16(v.y);
    __nv_bfloat16 hz = __float2bfloat16(v.z);
    __nv_bfloat16 hw = __float2bfloat16(v.w);
    __nv_bfloat16 lx = __float2bfloat16(v.x - __bfloat162float(hx));
    __nv_bfloat16 ly = __float2bfloat16(v.y - __bfloat162float(hy));
    __nv_bfloat16 lz = __float2bfloat16(v.z - __bfloat162float(hz));
    __nv_bfloat16 lw = __float2bfloat16(v.w - __bfloat162float(hw));
    __nv_bfloat162 a;
    a.x = hx; a.y = hy; hi[2 * i] = a;
    a.x = hz; a.y = hw; hi[2 * i + 1] = a;
    a.x = lx; a.y = ly; lo[2 * i] = a;
    a.x = lz; a.y = lw; lo[2 * i + 1] = a;
}

// ---------------------------------------------------------------------------
// Fused RoPE + head-major relayout + hi/lo bf16 split of q,k,v.
// ---------------------------------------------------------------------------
__device__ __forceinline__ void split_store4(__nv_bfloat16* ph, __nv_bfloat16* pl,
                                             float a, float b, float c, float d)
{
    __nv_bfloat16 h0 = __float2bfloat16(a), h1 = __float2bfloat16(b);
    __nv_bfloat16 h2 = __float2bfloat16(c), h3 = __float2bfloat16(d);
    __nv_bfloat162 v;
    v.x = h0; v.y = h1; *(__nv_bfloat162*)ph = v;
    v.x = h2; v.y = h3; *(__nv_bfloat162*)(ph + 2) = v;
    v.x = __float2bfloat16(a - __bfloat162float(h0));
    v.y = __float2bfloat16(b - __bfloat162float(h1));
    *(__nv_bfloat162*)pl = v;
    v.x = __float2bfloat16(c - __bfloat162float(h2));
    v.y = __float2bfloat16(d - __bfloat162float(h3));
    *(__nv_bfloat162*)(pl + 2) = v;
}

__global__ void rope_split(const float* __restrict__ cosp,
                           const float* __restrict__ sinp)
{
    int idx = blockIdx.x * 256 + threadIdx.x;
    int ds = idx & 7;
    int h  = (idx >> 3) & 15;
    int t  = (idx >> 7) & 2047;
    int b  = idx >> 18;
    int d0 = ds * 4;

    const float* base = g_qkv + ((size_t)(b * Tt + t)) * (3 * Cc) + h * Dd;
    float4 q1 = *(const float4*)(base + d0);
    float4 q2 = *(const float4*)(base + d0 + 32);
    float4 k1 = *(const float4*)(base + Cc + d0);
    float4 k2 = *(const float4*)(base + Cc + d0 + 32);
    float4 v1 = *(const float4*)(base + 2 * Cc + d0);
    float4 v2 = *(const float4*)(base + 2 * Cc + d0 + 32);
    float4 cw = *(const float4*)(cosp + t * Dd + d0);
    float4 sw = *(const float4*)(sinp + t * Dd + d0);

    const float sc = 0.125f;
    float qa0 = (q1.x * cw.x - q2.x * sw.x) * sc;
    float qa1 = (q1.y * cw.y - q2.y * sw.y) * sc;
    float qa2 = (q1.z * cw.z - q2.z * sw.z) * sc;
    float qa3 = (q1.w * cw.w - q2.w * sw.w) * sc;
    float qb0 = (q2.x * cw.x + q1.x * sw.x) * sc;
    float qb1 = (q2.y * cw.y + q1.y * sw.y) * sc;
    float qb2 = (q2.z * cw.z + q1.z * sw.z) * sc;
    float qb3 = (q2.w * cw.w + q1.w * sw.w) * sc;
    float ka0 = k1.x * cw.x - k2.x * sw.x;
    float ka1 = k1.y * cw.y - k2.y * sw.y;
    float ka2 = k1.z * cw.z - k2.z * sw.z;
    float ka3 = k1.w * cw.w - k2.w * sw.w;
    float kb0 = k2.x * cw.x + k1.x * sw.x;
    float kb1 = k2.y * cw.y + k1.y * sw.y;
    float kb2 = k2.z * cw.z + k1.z * sw.z;
    float kb3 = k2.w * cw.w + k1.w * sw.w;

    size_t ob = (((size_t)(b * NHh + h)) * Tt + t) * Dd;
    split_store4(g_qh + ob + d0,      g_ql + ob + d0,      qa0, qa1, qa2, qa3);
    split_store4(g_qh + ob + d0 + 32, g_ql + ob + d0 + 32, qb0, qb1, qb2, qb3);
    split_store4(g_kh + ob + d0,      g_kl + ob + d0,      ka0, ka1, ka2, ka3);
    split_store4(g_kh + ob + d0 + 32, g_kl + ob + d0 + 32, kb0, kb1, kb2, kb3);
    split_store4(g_vh + ob + d0,      g_vl + ob + d0,      v1.x, v1.y, v1.z, v1.w);
    split_store4(g_vh + ob + d0 + 32, g_vl + ob + d0 + 32, v2.x, v2.y, v2.z, v2.w);
}

// ---------------------------------------------------------------------------
// Flash attention on mma.sync (bf16 hi/lo split, fp32 softmax).
// Epilogue writes hi/lo bf16 directly to g_ah/g_al (proj GEMM inputs).
// ---------------------------------------------------------------------------
#define SROW 72
#define TILE_B 9216u

__global__ __launch_bounds__(128, 1) void flash_mma()
{
    extern __shared__ char fsm[];
    const uint32_t sb = smem_u32(fsm);

    const int bh = blockIdx.y;
    const int qt = (gridDim.x - 1) - blockIdx.x;
    const int q0 = qt * 64;
    const int tid = threadIdx.x, wid = tid >> 5, lane = tid & 31;

    const size_t hb = (size_t)bh * Tt * Dd;
    const __nv_bfloat16* Qh = g_qh + hb + (size_t)q0 * Dd;
    const __nv_bfloat16* Ql = g_ql + hb + (size_t)q0 * Dd;
    const __nv_bfloat16* Kh = g_kh + hb;
    const __nv_bfloat16* Kl = g_kl + hb;
    const __nv_bfloat16* Vh = g_vh + hb;
    const __nv_bfloat16* Vl = g_vl + hb;

    auto soff = [&](int buf, int mat) -> uint32_t {
        return sb + (uint32_t)(buf * 4 + mat) * TILE_B;
    };

    {
#pragma unroll
        for (int i = 0; i < 4; i++) {
            int lin = tid + i * 128;
            int r = lin >> 3, c = (lin & 7) * 8;
            uint32_t so = (uint32_t)(r * SROW + c) * 2;
            cp16(soff(1, 0) + so, Qh + (size_t)r * Dd + c);
            cp16(soff(1, 1) + so, Ql + (size_t)r * Dd + c);
        }
        CP_COMMIT();
#pragma unroll
        for (int i = 0; i < 4; i++) {
            int lin = tid + i * 128;
            int r = lin >> 3, c = (lin & 7) * 8;
            uint32_t so = (uint32_t)(r * SROW + c) * 2;
            cp16(soff(0, 0) + so, Kh + (size_t)r * Dd + c);
            cp16(soff(0, 1) + so, Kl + (size_t)r * Dd + c);
            cp16(soff(0, 2) + so, Vh + (size_t)r * Dd + c);
            cp16(soff(0, 3) + so, Vl + (size_t)r * Dd + c);
        }
        CP_COMMIT();
        CP_WAIT0();
        __syncthreads();
    }

    uint32_t QHf[4][4], QLf[4][4];
    {
        const int row = wid * 16 + (lane & 15);
        const int ck  = (lane >> 4) * 8;
#pragma unroll
        for (int kk = 0; kk < 4; kk++) {
            uint32_t ao = (uint32_t)(row * SROW + kk * 16 + ck) * 2;
            ldmx4(QHf[kk][0], QHf[kk][1], QHf[kk][2], QHf[kk][3], soff(1, 0) + ao);
            ldmx4(QLf[kk][0], QLf[kk][1], QLf[kk][2], QLf[kk][3], soff(1, 1) + ao);
        }
    }

    float O[8][4];
#pragma unroll
    for (int i = 0; i < 8; i++)
#pragma unroll
        for (int e = 0; e < 4; e++) O[i][e] = 0.f;
    float m0 = -1e30f, m1 = -1e30f, l0 = 0.f, l1 = 0.f;

    const int klrow = lane & 15;
    const int klk   = (lane >> 4) * 8;
    const int vg    = lane >> 3;
    const int vrow_in = (vg & 1) * 8 + (lane & 7);
    const int vcol_of = (vg >> 1) * 8;

    for (int jt = 0; jt <= qt; jt++) {
        const int buf = jt & 1;
        __syncthreads();
        if (jt < qt) {
            const int j1 = (jt + 1) * 64;
#pragma unroll
            for (int i = 0; i < 4; i++) {
                int lin = tid + i * 128;
                int r = lin >> 3, c = (lin & 7) * 8;
                uint32_t so = (uint32_t)(r * SROW + c) * 2;
                size_t gi = (size_t)(j1 + r) * Dd + c;
                cp16(soff(buf ^ 1, 0) + so, Kh + gi);
                cp16(soff(buf ^ 1, 1) + so, Kl + gi);
                cp16(soff(buf ^ 1, 2) + so, Vh + gi);
                cp16(soff(buf ^ 1, 3) + so, Vl + gi);
            }
            CP_COMMIT();
            CP_WAIT1();
        } else {
            CP_WAIT0();
        }
        __syncthreads();

        float S[8][4];
#pragma unroll
        for (int i = 0; i < 8; i++)
#pragma unroll
            for (int e = 0; e < 4; e++) S[i][e] = 0.f;

#pragma unroll
        for (int jg = 0; jg < 4; jg++) {
#pragma unroll
            for (int kk = 0; kk < 4; kk++) {
                uint32_t ao = (uint32_t)((jg * 16 + klrow) * SROW + kk * 16 + klk) * 2;
                uint32_t kh0, kh1, kh2, kh3, kl0, kl1, kl2, kl3;
                ldmx4(kh0, kh1, kh2, kh3, soff(buf, 0) + ao);
                ldmx4(kl0, kl1, kl2, kl3, soff(buf, 1) + ao);
                mma16816(S[jg * 2 + 0], QHf[kk], kh0, kh2);
                mma16816(S[jg * 2 + 0], QLf[kk], kh0, kh2);
                mma16816(S[jg * 2 + 0], QHf[kk], kl0, kl2);
                mma16816(S[jg * 2 + 1], QHf[kk], kh1, kh3);
                mma16816(S[jg * 2 + 1], QLf[kk], kh1, kh3);
                mma16816(S[jg * 2 + 1], QHf[kk], kl1, kl3);
            }
        }

        if (jt == qt) {
            const int r0l = wid * 16 + (lane >> 2);
            const int cb  = (lane & 3) * 2;
#pragma unroll
            for (int nf = 0; nf < 8; nf++) {
                int c0 = nf * 8 + cb;
                if (c0     > r0l)     S[nf][0] = -1e30f;
                if (c0 + 1 > r0l)     S[nf][1] = -1e30f;
                if (c0     > r0l + 8) S[nf][2] = -1e30f;
                if (c0 + 1 > r0l + 8) S[nf][3] = -1e30f;
            }
        }

        float tm0 = -1e30f, tm1 = -1e30f;
#pragma unroll
        for (int nf = 0; nf < 8; nf++) {
            tm0 = fmaxf(tm0, fmaxf(S[nf][0], S[nf][1]));
            tm1 = fmaxf(tm1, fmaxf(S[nf][2], S[nf][3]));
        }
        tm0 = fmaxf(tm0, __shfl_xor_sync(0xffffffff, tm0, 1));
        tm0 = fmaxf(tm0, __shfl_xor_sync(0xffffffff, tm0, 2));
        tm1 = fmaxf(tm1, __shfl_xor_sync(0xffffffff, tm1, 1));
        tm1 = fmaxf(tm1, __shfl_xor_sync(0xffffffff, tm1, 2));

        float m0n = fmaxf(m0, tm0), m1n = fmaxf(m1, tm1);
        float sc0 = __expf(m0 - m0n), sc1 = __expf(m1 - m1n);
        l0 *= sc0; l1 *= sc1;
#pragma unroll
        for (int i = 0; i < 8; i++) {
            O[i][0] *= sc0; O[i][1] *= sc0;
            O[i][2] *= sc1; O[i][3] *= sc1;
        }
#pragma unroll
        for (int nf = 0; nf < 8; nf++) {
            S[nf][0] = __expf(S[nf][0] - m0n);
            S[nf][1] = __expf(S[nf][1] - m0n);
            S[nf][2] = __expf(S[nf][2] - m1n);
            S[nf][3] = __expf(S[nf][3] - m1n);
            l0 += S[nf][0] + S[nf][1];
            l1 += S[nf][2] + S[nf][3];
        }
        m0 = m0n; m1 = m1n;

#pragma unroll
        for (int kk = 0; kk < 4; kk++) {
            const float* s0 = S[2 * kk];
            const float* s1 = S[2 * kk + 1];
            uint32_t PH[4], PL[4];
            PH[0] = packbf(s0[0], s0[1]);
            PH[1] = packbf(s0[2], s0[3]);
            PH[2] = packbf(s1[0], s1[1]);
            PH[3] = packbf(s1[2], s1[3]);
#pragma unroll
            for (int e = 0; e < 4; e++) {
                const float* sv = (e < 2) ? s0 : s1;
                float c0 = sv[(e & 1) * 2], c1 = sv[(e & 1) * 2 + 1];
                float f0 = __uint_as_float(PH[e] << 16);
                float f1 = __uint_as_float(PH[e] & 0xffff0000u);
                PL[e] = packbf(c0 - f0, c1 - f1);
            }
#pragma unroll
            for (int dc = 0; dc < 4; dc++) {
                uint32_t vo = (uint32_t)((kk * 16 + vrow_in) * SROW + dc * 16 + vcol_of) * 2;
                uint32_t vh0, vh1, vh2, vh3, vl0, vl1, vl2, vl3;
                ldmx4t(vh0, vh1, vh2, vh3, soff(buf, 2) + vo);
                ldmx4t(vl0, vl1, vl2, vl3, soff(buf, 3) + vo);
                mma16816(O[dc * 2 + 0], PH, vh0, vh1);
                mma16816(O[dc * 2 + 0], PL, vh0, vh1);
                mma16816(O[dc * 2 + 0], PH, vl0, vl1);
                mma16816(O[dc * 2 + 1], PH, vh2, vh3);
                mma16816(O[dc * 2 + 1], PL, vh2, vh3);
                mma16816(O[dc * 2 + 1], PH, vl2, vl3);
            }
        }
    }

    l0 += __shfl_xor_sync(0xffffffff, l0, 1);
    l0 += __shfl_xor_sync(0xffffffff, l0, 2);
    l1 += __shfl_xor_sync(0xffffffff, l1, 1);
    l1 += __shfl_xor_sync(0xffffffff, l1, 2);
    const float i0 = 1.f / l0, i1 = 1.f / l1;

    // Epilogue: write hi/lo bf16 directly (proj GEMM inputs)
    const int b = bh >> 4, h = bh & 15;
    const int t0 = q0 + wid * 16 + (lane >> 2);
    const int t1 = t0 + 8;
    const size_t co = (size_t)h * Dd + (lane & 3) * 2;
    __nv_bfloat16* ah0 = g_ah + ((size_t)(b * Tt + t0)) * Cc + co;
    __nv_bfloat16* al0 = g_al + ((size_t)(b * Tt + t0)) * Cc + co;
    __nv_bfloat16* ah1 = g_ah + ((size_t)(b * Tt + t1)) * Cc + co;
    __nv_bfloat16* al1 = g_al + ((size_t)(b * Tt + t1)) * Cc + co;
#pragma unroll
    for (int nf = 0; nf < 8; nf++) {
        float v0 = O[nf][0] * i0, v1 = O[nf][1] * i0;
        float v2 = O[nf][2] * i1, v3 = O[nf][3] * i1;
        __nv_bfloat16 h0 = __float2bfloat16(v0), h1 = __float2bfloat16(v1);
        __nv_bfloat16 h2 = __float2bfloat16(v2), h3 = __float2bfloat16(v3);
        __nv_bfloat162 w;
        w.x = h0; w.y = h1; *(__nv_bfloat162*)(ah0 + nf * 8) = w;
        w.x = h2; w.y = h3; *(__nv_bfloat162*)(ah1 + nf * 8) = w;
        w.x = __float2bfloat16(v0 - __bfloat162float(h0));
        w.y = __float2bfloat16(v1 - __bfloat162float(h1));
        *(__nv_bfloat162*)(al0 + nf * 8) = w;
        w.x = __float2bfloat16(v2 - __bfloat162float(h2));
        w.y = __float2bfloat16(v3 - __bfloat162float(h3));
        *(__nv_bfloat162*)(al1 + nf * 8) = w;
    }
}

// ---------------------------------------------------------------------------
extern "C" void kernel_launch(void* const* d_in, const int* in_sizes, int n_in,
                              void* d_out, int out_size)
{
    const float* x      = (const float*)d_in[0];
    const float* w_attn = (const float*)d_in[1];
    const float* b_attn = (const float*)d_in[2];
    const float* w_proj = (const float*)d_in[3];
    const float* b_proj = (const float*)d_in[4];
    const float* cosp   = (const float*)d_in[5];
    const float* sinp   = (const float*)d_in[6];
    float* out = (float*)d_out;

    void *p_xh, *p_xl, *p_wh, *p_wl, *p_ph, *p_pl, *p_ah, *p_al, *p_qkv;
    cudaGetSymbolAddress(&p_xh, g_xh);
    cudaGetSymbolAddress(&p_xl, g_xl);
    cudaGetSymbolAddress(&p_wh, g_wh);
    cudaGetSymbolAddress(&p_wl, g_wl);
    cudaGetSymbolAddress(&p_ph, g_ph);
    cudaGetSymbolAddress(&p_pl, g_pl);
    cudaGetSymbolAddress(&p_ah, g_ah);
    cudaGetSymbolAddress(&p_al, g_al);
    cudaGetSymbolAddress(&p_qkv, g_qkv);

    static bool once = false;
    if (!once) {
        cudaFuncSetAttribute(flash_mma,
                             cudaFuncAttributeMaxDynamicSharedMemorySize, 8 * TILE_B);
        cudaFuncSetAttribute(gemm_bf16x3,
                             cudaFuncAttributeMaxDynamicSharedMemorySize, GEMM_SMEM);
        once = true;
    }

    // 1) splits of x, w_attn, w_proj
    {
        int n4 = (Mtot * Cc) / 4;
        split_fp32_bf16<<<(n4 + 255) / 256, 256>>>(
            (const float4*)x, (__nv_bfloat162*)p_xh, (__nv_bfloat162*)p_xl, n4);
    }
    {
        int n4 = (3 * Cc * Cc) / 4;
        split_fp32_bf16<<<(n4 + 255) / 256, 256>>>(
            (const float4*)w_attn, (__nv_bfloat162*)p_wh, (__nv_bfloat162*)p_wl, n4);
    }
    {
        int n4 = (Cc * Cc) / 4;
        split_fp32_bf16<<<(n4 + 255) / 256, 256>>>(
            (const float4*)w_proj, (__nv_bfloat162*)p_ph, (__nv_bfloat162*)p_pl, n4);
    }

    // 2) QKV projection (pipelined tensor-core GEMM) -> g_qkv fp32
    {
        dim3 grid((3 * Cc) / 128, Mtot / 128);
        gemm_bf16x3<<<grid, 256, GEMM_SMEM>>>(
            (const __nv_bfloat16*)p_xh, (const __nv_bfloat16*)p_xl,
            (const __nv_bfloat16*)p_wh, (const __nv_bfloat16*)p_wl,
            b_attn, (float*)p_qkv, 3 * Cc, Cc);
    }

    // 3) fused RoPE + relayout + bf16 split of q,k,v
    {
        int total = Bb * Tt * NHh * 8;
        rope_split<<<total / 256, 256>>>(cosp, sinp);
    }

    // 4) flash attention -> g_ah/g_al bf16 (direct)
    {
        dim3 grid(Tt / 64, Bb * NHh);
        flash_mma<<<grid, 128, 8 * TILE_B>>>();
    }

    // 5) output projection
    {
        dim3 grid(Cc / 128, Mtot / 128);
        gemm_bf16x3<<<grid, 256, GEMM_SMEM>>>(
            (const __nv_bfloat16*)p_ah, (const __nv_bfloat16*)p_al,
            (const __nv_bfloat16*)p_ph, (const __nv_bfloat16*)p_pl,
            b_proj, out, Cc, Cc);
    }
}

// round 6
// speedup vs baseline: 5.6373x; 1.0804x over previous
#include <cuda_runtime.h>
#include <cuda_bf16.h>
#include <cstdint>

#define Bb 4
#define Tt 2048
#define Cc 1024
#define NHh 16
#define Dd 64
#define Mtot (Bb * Tt)   // 8192

// ------------------------- scratch (__device__ globals) --------------------
__device__ float g_qkv[(size_t)Bb * Tt * 3 * Cc];    // [B,T,3C] fp32
__device__ __nv_bfloat16 g_xh[(size_t)Mtot * Cc];
__device__ __nv_bfloat16 g_xl[(size_t)Mtot * Cc];
__device__ __nv_bfloat16 g_wh[(size_t)3 * Cc * Cc];
__device__ __nv_bfloat16 g_wl[(size_t)3 * Cc * Cc];
__device__ __nv_bfloat16 g_ph[(size_t)Cc * Cc];
__device__ __nv_bfloat16 g_pl[(size_t)Cc * Cc];
__device__ __nv_bfloat16 g_ah[(size_t)Mtot * Cc];
__device__ __nv_bfloat16 g_al[(size_t)Mtot * Cc];
// head-major [b*16+h][t][d] bf16 for attention
__device__ __nv_bfloat16 g_qh[(size_t)Mtot * Cc];
__device__ __nv_bfloat16 g_ql[(size_t)Mtot * Cc];
__device__ __nv_bfloat16 g_kh[(size_t)Mtot * Cc];
__device__ __nv_bfloat16 g_kl[(size_t)Mtot * Cc];
__device__ __nv_bfloat16 g_vh[(size_t)Mtot * Cc];
__device__ __nv_bfloat16 g_vl[(size_t)Mtot * Cc];

// ------------------------- helpers -----------------------------------------
__device__ __forceinline__ uint32_t smem_u32(const void* p) {
    uint32_t a;
    asm("{ .reg .u64 t; cvta.to.shared.u64 t, %1; cvt.u32.u64 %0, t; }"
        : "=r"(a) : "l"(p));
    return a;
}

__device__ __forceinline__ void ldmx4(uint32_t& r0, uint32_t& r1,
                                      uint32_t& r2, uint32_t& r3, uint32_t addr) {
    asm volatile("ldmatrix.sync.aligned.m8n8.x4.shared.b16 {%0,%1,%2,%3}, [%4];"
                 : "=r"(r0), "=r"(r1), "=r"(r2), "=r"(r3) : "r"(addr));
}

__device__ __forceinline__ void ldmx4t(uint32_t& r0, uint32_t& r1,
                                       uint32_t& r2, uint32_t& r3, uint32_t addr) {
    asm volatile("ldmatrix.sync.aligned.m8n8.x4.trans.shared.b16 {%0,%1,%2,%3}, [%4];"
                 : "=r"(r0), "=r"(r1), "=r"(r2), "=r"(r3) : "r"(addr));
}

__device__ __forceinline__ void mma16816(float* d, const uint32_t* a,
                                         uint32_t b0, uint32_t b1) {
    asm volatile(
        "mma.sync.aligned.m16n8k16.row.col.f32.bf16.bf16.f32 "
        "{%0,%1,%2,%3}, {%4,%5,%6,%7}, {%8,%9}, {%0,%1,%2,%3};"
        : "+f"(d[0]), "+f"(d[1]), "+f"(d[2]), "+f"(d[3])
        : "r"(a[0]), "r"(a[1]), "r"(a[2]), "r"(a[3]), "r"(b0), "r"(b1));
}

__device__ __forceinline__ uint32_t packbf(float lo, float hi) {
    uint32_t r;
    asm("cvt.rn.bf16x2.f32 %0, %1, %2;" : "=r"(r) : "f"(hi), "f"(lo));
    return r;
}

__device__ __forceinline__ void cp16(uint32_t dst, const void* src) {
    asm volatile("cp.async.cg.shared.global [%0], [%1], 16;" :: "r"(dst), "l"(src));
}
#define CP_COMMIT() asm volatile("cp.async.commit_group;" ::: "memory")
#define CP_WAIT0()  asm volatile("cp.async.wait_group 0;" ::: "memory")
#define CP_WAIT1()  asm volatile("cp.async.wait_group 1;" ::: "memory")

// ---------------------------------------------------------------------------
// bf16x3 GEMM via mma.sync, cp.async 2-stage pipelined, 2 CTAs/SM.
// C[M,N] = (Ah+Al)[M,K] @ (Bh+Bl)[N,K]^T + bias[N]
// CTA tile 128x128, BK=32, 8 warps (2m x 4n), warp tile 64x32.
// ---------------------------------------------------------------------------
#define SPAD 40
#define GMAT (128 * SPAD * 2u)   // bytes per matrix per stage (10240)

__global__ __launch_bounds__(256, 2)
void gemm_bf16x3(const __nv_bfloat16* __restrict__ Ah,
                 const __nv_bfloat16* __restrict__ Al,
                 const __nv_bfloat16* __restrict__ Bh,
                 const __nv_bfloat16* __restrict__ Bl,
                 const float* __restrict__ bias,
                 float* __restrict__ Cout, int N, int K)
{
    extern __shared__ char gsm[];
    const uint32_t sb = smem_u32(gsm);

    const int tid  = threadIdx.x;
    const int wid  = tid >> 5;
    const int lane = tid & 31;
    const int mw   = wid >> 2;
    const int nw   = wid & 3;
    const int m0   = blockIdx.y * 128;
    const int n0   = blockIdx.x * 128;

    auto stoff = [&](int s, int m) -> uint32_t {
        return sb + (uint32_t)(s * 4 + m) * GMAT;
    };

    const int r0i = tid >> 2, ci = tid & 3;
    const int r1i = r0i + 64;
    const uint32_t so0 = (uint32_t)(r0i * (SPAD * 2) + ci * 16);
    const uint32_t so1 = (uint32_t)(r1i * (SPAD * 2) + ci * 16);
    const int kq = K >> 3;
    const int nk = K >> 5;

    auto load_stage = [&](int s, int kc) {
        const size_t a0 = (size_t)(m0 + r0i) * kq + kc * 4 + ci;
        const size_t a1 = (size_t)(m0 + r1i) * kq + kc * 4 + ci;
        const size_t b0 = (size_t)(n0 + r0i) * kq + kc * 4 + ci;
        const size_t b1 = (size_t)(n0 + r1i) * kq + kc * 4 + ci;
        cp16(stoff(s, 0) + so0, (const uint4*)Ah + a0);
        cp16(stoff(s, 0) + so1, (const uint4*)Ah + a1);
        cp16(stoff(s, 1) + so0, (const uint4*)Al + a0);
        cp16(stoff(s, 1) + so1, (const uint4*)Al + a1);
        cp16(stoff(s, 2) + so0, (const uint4*)Bh + b0);
        cp16(stoff(s, 2) + so1, (const uint4*)Bh + b1);
        cp16(stoff(s, 3) + so0, (const uint4*)Bl + b0);
        cp16(stoff(s, 3) + so1, (const uint4*)Bl + b1);
    };

    const int lrow = lane & 15;
    const int lk   = (lane >> 4) * 8;
    uint32_t aoff[4], boff[2];
#pragma unroll
    for (int mt = 0; mt < 4; mt++)
        aoff[mt] = (uint32_t)(((mw * 64 + mt * 16 + lrow) * SPAD + lk) * 2);
#pragma unroll
    for (int ng = 0; ng < 2; ng++)
        boff[ng] = (uint32_t)(((nw * 32 + ng * 16 + lrow) * SPAD + lk) * 2);

    float acc[4][4][4];
#pragma unroll
    for (int i = 0; i < 4; i++)
#pragma unroll
        for (int j = 0; j < 4; j++)
#pragma unroll
            for (int e = 0; e < 4; e++) acc[i][j][e] = 0.f;

    load_stage(0, 0);
    CP_COMMIT();

    for (int kc = 0; kc < nk; kc++) {
        const int s = kc & 1;
        if (kc + 1 < nk) {
            load_stage(s ^ 1, kc + 1);
            CP_COMMIT();
            CP_WAIT1();
        } else {
            CP_WAIT0();
        }
        __syncthreads();

        const uint32_t uAh = stoff(s, 0), uAl = stoff(s, 1);
        const uint32_t uBh = stoff(s, 2), uBl = stoff(s, 3);
#pragma unroll
        for (int ks = 0; ks < 2; ks++) {
            const uint32_t kb = ks * 32;
            uint32_t ah[4][4], al[4][4];
#pragma unroll
            for (int mt = 0; mt < 4; mt++) {
                ldmx4(ah[mt][0], ah[mt][1], ah[mt][2], ah[mt][3], uAh + aoff[mt] + kb);
                ldmx4(al[mt][0], al[mt][1], al[mt][2], al[mt][3], uAl + aoff[mt] + kb);
            }
            uint32_t bh[2][4], bl[2][4];
#pragma unroll
            for (int ng = 0; ng < 2; ng++) {
                ldmx4(bh[ng][0], bh[ng][1], bh[ng][2], bh[ng][3], uBh + boff[ng] + kb);
                ldmx4(bl[ng][0], bl[ng][1], bl[ng][2], bl[ng][3], uBl + boff[ng] + kb);
            }
#pragma unroll
            for (int mt = 0; mt < 4; mt++) {
#pragma unroll
                for (int ng = 0; ng < 2; ng++) {
#pragma unroll
                    for (int sub = 0; sub < 2; sub++) {
                        const int nt = ng * 2 + sub;
                        const uint32_t bh0 = bh[ng][sub], bh1 = bh[ng][sub + 2];
                        const uint32_t bl0 = bl[ng][sub], bl1 = bl[ng][sub + 2];
                        mma16816(acc[mt][nt], ah[mt], bh0, bh1);
                        mma16816(acc[mt][nt], ah[mt], bl0, bl1);
                        mma16816(acc[mt][nt], al[mt], bh0, bh1);
                    }
                }
            }
        }
        __syncthreads();
    }

    const int erow = lane >> 2;
    const int ecol = (lane & 3) * 2;
#pragma unroll
    for (int mt = 0; mt < 4; mt++) {
#pragma unroll
        for (int nt = 0; nt < 4; nt++) {
            const int row = m0 + mw * 64 + mt * 16 + erow;
            const int col = n0 + nw * 32 + nt * 8 + ecol;
            const float b0 = bias[col], b1 = bias[col + 1];
            float2 v;
            v.x = acc[mt][nt][0] + b0;
            v.y = acc[mt][nt][1] + b1;
            *(float2*)(Cout + (size_t)row * N + col) = v;
            v.x = acc[mt][nt][2] + b0;
            v.y = acc[mt][nt][3] + b1;
            *(float2*)(Cout + (size_t)(row + 8) * N + col) = v;
        }
    }
}
#define GEMM_SMEM (2u * 4u * GMAT)   // 81920

// ---------------------------------------------------------------------------
// fp32 -> (hi,lo) bf16 split, vectorized by 4
// ---------------------------------------------------------------------------
__global__ void split_fp32_bf16(const float4* __restrict__ src,
                                __nv_bfloat162* __restrict__ hi,
                                __nv_bfloat162* __restrict__ lo, int n4)
{
    int i = blockIdx.x * 256 + threadIdx.x;
    if (i >= n4) return;
    float4 v = src[i];
    __nv_bfloat16 hx = __float2bfloat16(v.x);
    __nv_bfloat16 hy = __float2bfloat16(v.y);
    __nv_bfloat16 hz = __float2bfloat16(v.z);
    __nv_bfloat16 hw = __float2bfloat16(v.w);
    __nv_bfloat16 lx = __float2bfloat16(v.x - __bfloat162float(hx));
    __nv_bfloat16 ly = __float2bfloat16(v.y - __bfloat162float(hy));
    __nv_bfloat16 lz = __float2bfloat16(v.z - __bfloat162float(hz));
    __nv_bfloat16 lw = __float2bfloat16(v.w - __bfloat162float(hw));
    __nv_bfloat162 a;
    a.x = hx; a.y = hy; hi[2 * i] = a;
    a.x = hz; a.y = hw; hi[2 * i + 1] = a;
    a.x = lx; a.y = ly; lo[2 * i] = a;
    a.x = lz; a.y = lw; lo[2 * i + 1] = a;
}

// ---------------------------------------------------------------------------
// Fused RoPE + head-major relayout + hi/lo bf16 split of q,k,v.
// ---------------------------------------------------------------------------
__device__ __forceinline__ void split_store4(__nv_bfloat16* ph, __nv_bfloat16* pl,
                                             float a, float b, float c, float d)
{
    __nv_bfloat16 h0 = __float2bfloat16(a), h1 = __float2bfloat16(b);
    __nv_bfloat16 h2 = __float2bfloat16(c), h3 = __float2bfloat16(d);
    __nv_bfloat162 v;
    v.x = h0; v.y = h1; *(__nv_bfloat162*)ph = v;
    v.x = h2; v.y = h3; *(__nv_bfloat162*)(ph + 2) = v;
    v.x = __float2bfloat16(a - __bfloat162float(h0));
    v.y = __float2bfloat16(b - __bfloat162float(h1));
    *(__nv_bfloat162*)pl = v;
    v.x = __float2bfloat16(c - __bfloat162float(h2));
    v.y = __float2bfloat16(d - __bfloat162float(h3));
    *(__nv_bfloat162*)(pl + 2) = v;
}

__global__ void rope_split(const float* __restrict__ cosp,
                           const float* __restrict__ sinp)
{
    int idx = blockIdx.x * 256 + threadIdx.x;
    int ds = idx & 7;
    int h  = (idx >> 3) & 15;
    int t  = (idx >> 7) & 2047;
    int b  = idx >> 18;
    int d0 = ds * 4;

    const float* base = g_qkv + ((size_t)(b * Tt + t)) * (3 * Cc) + h * Dd;
    float4 q1 = *(const float4*)(base + d0);
    float4 q2 = *(const float4*)(base + d0 + 32);
    float4 k1 = *(const float4*)(base + Cc + d0);
    float4 k2 = *(const float4*)(base + Cc + d0 + 32);
    float4 v1 = *(const float4*)(base + 2 * Cc + d0);
    float4 v2 = *(const float4*)(base + 2 * Cc + d0 + 32);
    float4 cw = *(const float4*)(cosp + t * Dd + d0);
    float4 sw = *(const float4*)(sinp + t * Dd + d0);

    const float sc = 0.125f;
    float qa0 = (q1.x * cw.x - q2.x * sw.x) * sc;
    float qa1 = (q1.y * cw.y - q2.y * sw.y) * sc;
    float qa2 = (q1.z * cw.z - q2.z * sw.z) * sc;
    float qa3 = (q1.w * cw.w - q2.w * sw.w) * sc;
    float qb0 = (q2.x * cw.x + q1.x * sw.x) * sc;
    float qb1 = (q2.y * cw.y + q1.y * sw.y) * sc;
    float qb2 = (q2.z * cw.z + q1.z * sw.z) * sc;
    float qb3 = (q2.w * cw.w + q1.w * sw.w) * sc;
    float ka0 = k1.x * cw.x - k2.x * sw.x;
    float ka1 = k1.y * cw.y - k2.y * sw.y;
    float ka2 = k1.z * cw.z - k2.z * sw.z;
    float ka3 = k1.w * cw.w - k2.w * sw.w;
    float kb0 = k2.x * cw.x + k1.x * sw.x;
    float kb1 = k2.y * cw.y + k1.y * sw.y;
    float kb2 = k2.z * cw.z + k1.z * sw.z;
    float kb3 = k2.w * cw.w + k1.w * sw.w;

    size_t ob = (((size_t)(b * NHh + h)) * Tt + t) * Dd;
    split_store4(g_qh + ob + d0,      g_ql + ob + d0,      qa0, qa1, qa2, qa3);
    split_store4(g_qh + ob + d0 + 32, g_ql + ob + d0 + 32, qb0, qb1, qb2, qb3);
    split_store4(g_kh + ob + d0,      g_kl + ob + d0,      ka0, ka1, ka2, ka3);
    split_store4(g_kh + ob + d0 + 32, g_kl + ob + d0 + 32, kb0, kb1, kb2, kb3);
    split_store4(g_vh + ob + d0,      g_vl + ob + d0,      v1.x, v1.y, v1.z, v1.w);
    split_store4(g_vh + ob + d0 + 32, g_vl + ob + d0 + 32, v2.x, v2.y, v2.z, v2.w);
}

// ---------------------------------------------------------------------------
// Flash attention on mma.sync (bf16 hi/lo split, fp32 softmax).
// ---------------------------------------------------------------------------
#define SROW 72
#define TILE_B 9216u

__global__ __launch_bounds__(128, 1) void flash_mma()
{
    extern __shared__ char fsm[];
    const uint32_t sb = smem_u32(fsm);

    const int bh = blockIdx.y;
    const int qt = (gridDim.x - 1) - blockIdx.x;
    const int q0 = qt * 64;
    const int tid = threadIdx.x, wid = tid >> 5, lane = tid & 31;

    const size_t hb = (size_t)bh * Tt * Dd;
    const __nv_bfloat16* Qh = g_qh + hb + (size_t)q0 * Dd;
    const __nv_bfloat16* Ql = g_ql + hb + (size_t)q0 * Dd;
    const __nv_bfloat16* Kh = g_kh + hb;
    const __nv_bfloat16* Kl = g_kl + hb;
    const __nv_bfloat16* Vh = g_vh + hb;
    const __nv_bfloat16* Vl = g_vl + hb;

    auto soff = [&](int buf, int mat) -> uint32_t {
        return sb + (uint32_t)(buf * 4 + mat) * TILE_B;
    };

    {
#pragma unroll
        for (int i = 0; i < 4; i++) {
            int lin = tid + i * 128;
            int r = lin >> 3, c = (lin & 7) * 8;
            uint32_t so = (uint32_t)(r * SROW + c) * 2;
            cp16(soff(1, 0) + so, Qh + (size_t)r * Dd + c);
            cp16(soff(1, 1) + so, Ql + (size_t)r * Dd + c);
        }
        CP_COMMIT();
#pragma unroll
        for (int i = 0; i < 4; i++) {
            int lin = tid + i * 128;
            int r = lin >> 3, c = (lin & 7) * 8;
            uint32_t so = (uint32_t)(r * SROW + c) * 2;
            cp16(soff(0, 0) + so, Kh + (size_t)r * Dd + c);
            cp16(soff(0, 1) + so, Kl + (size_t)r * Dd + c);
            cp16(soff(0, 2) + so, Vh + (size_t)r * Dd + c);
            cp16(soff(0, 3) + so, Vl + (size_t)r * Dd + c);
        }
        CP_COMMIT();
        CP_WAIT0();
        __syncthreads();
    }

    uint32_t QHf[4][4], QLf[4][4];
    {
        const int row = wid * 16 + (lane & 15);
        const int ck  = (lane >> 4) * 8;
#pragma unroll
        for (int kk = 0; kk < 4; kk++) {
            uint32_t ao = (uint32_t)(row * SROW + kk * 16 + ck) * 2;
            ldmx4(QHf[kk][0], QHf[kk][1], QHf[kk][2], QHf[kk][3], soff(1, 0) + ao);
            ldmx4(QLf[kk][0], QLf[kk][1], QLf[kk][2], QLf[kk][3], soff(1, 1) + ao);
        }
    }

    float O[8][4];
#pragma unroll
    for (int i = 0; i < 8; i++)
#pragma unroll
        for (int e = 0; e < 4; e++) O[i][e] = 0.f;
    float m0 = -1e30f, m1 = -1e30f, l0 = 0.f, l1 = 0.f;

    const int klrow = lane & 15;
    const int klk   = (lane >> 4) * 8;
    const int vg    = lane >> 3;
    const int vrow_in = (vg & 1) * 8 + (lane & 7);
    const int vcol_of = (vg >> 1) * 8;

    for (int jt = 0; jt <= qt; jt++) {
        const int buf = jt & 1;
        __syncthreads();
        if (jt < qt) {
            const int j1 = (jt + 1) * 64;
#pragma unroll
            for (int i = 0; i < 4; i++) {
                int lin = tid + i * 128;
                int r = lin >> 3, c = (lin & 7) * 8;
                uint32_t so = (uint32_t)(r * SROW + c) * 2;
                size_t gi = (size_t)(j1 + r) * Dd + c;
                cp16(soff(buf ^ 1, 0) + so, Kh + gi);
                cp16(soff(buf ^ 1, 1) + so, Kl + gi);
                cp16(soff(buf ^ 1, 2) + so, Vh + gi);
                cp16(soff(buf ^ 1, 3) + so, Vl + gi);
            }
            CP_COMMIT();
            CP_WAIT1();
        } else {
            CP_WAIT0();
        }
        __syncthreads();

        float S[8][4];
#pragma unroll
        for (int i = 0; i < 8; i++)
#pragma unroll
            for (int e = 0; e < 4; e++) S[i][e] = 0.f;

#pragma unroll
        for (int jg = 0; jg < 4; jg++) {
#pragma unroll
            for (int kk = 0; kk < 4; kk++) {
                uint32_t ao = (uint32_t)((jg * 16 + klrow) * SROW + kk * 16 + klk) * 2;
                uint32_t kh0, kh1, kh2, kh3, kl0, kl1, kl2, kl3;
                ldmx4(kh0, kh1, kh2, kh3, soff(buf, 0) + ao);
                ldmx4(kl0, kl1, kl2, kl3, soff(buf, 1) + ao);
                mma16816(S[jg * 2 + 0], QHf[kk], kh0, kh2);
                mma16816(S[jg * 2 + 0], QLf[kk], kh0, kh2);
                mma16816(S[jg * 2 + 0], QHf[kk], kl0, kl2);
                mma16816(S[jg * 2 + 1], QHf[kk], kh1, kh3);
                mma16816(S[jg * 2 + 1], QLf[kk], kh1, kh3);
                mma16816(S[jg * 2 + 1], QHf[kk], kl1, kl3);
            }
        }

        if (jt == qt) {
            const int r0l = wid * 16 + (lane >> 2);
            const int cb  = (lane & 3) * 2;
#pragma unroll
            for (int nf = 0; nf < 8; nf++) {
                int c0 = nf * 8 + cb;
                if (c0     > r0l)     S[nf][0] = -1e30f;
                if (c0 + 1 > r0l)     S[nf][1] = -1e30f;
                if (c0     > r0l + 8) S[nf][2] = -1e30f;
                if (c0 + 1 > r0l + 8) S[nf][3] = -1e30f;
            }
        }

        float tm0 = -1e30f, tm1 = -1e30f;
#pragma unroll
        for (int nf = 0; nf < 8; nf++) {
            tm0 = fmaxf(tm0, fmaxf(S[nf][0], S[nf][1]));
            tm1 = fmaxf(tm1, fmaxf(S[nf][2], S[nf][3]));
        }
        tm0 = fmaxf(tm0, __shfl_xor_sync(0xffffffff, tm0, 1));
        tm0 = fmaxf(tm0, __shfl_xor_sync(0xffffffff, tm0, 2));
        tm1 = fmaxf(tm1, __shfl_xor_sync(0xffffffff, tm1, 1));
        tm1 = fmaxf(tm1, __shfl_xor_sync(0xffffffff, tm1, 2));

        float m0n = fmaxf(m0, tm0), m1n = fmaxf(m1, tm1);
        float sc0 = __expf(m0 - m0n), sc1 = __expf(m1 - m1n);
        l0 *= sc0; l1 *= sc1;
#pragma unroll
        for (int i = 0; i < 8; i++) {
            O[i][0] *= sc0; O[i][1] *= sc0;
            O[i][2] *= sc1; O[i][3] *= sc1;
        }
#pragma unroll
        for (int nf = 0; nf < 8; nf++) {
            S[nf][0] = __expf(S[nf][0] - m0n);
            S[nf][1] = __expf(S[nf][1] - m0n);
            S[nf][2] = __expf(S[nf][2] - m1n);
            S[nf][3] = __expf(S[nf][3] - m1n);
            l0 += S[nf][0] + S[nf][1];
            l1 += S[nf][2] + S[nf][3];
        }
        m0 = m0n; m1 = m1n;

#pragma unroll
        for (int kk = 0; kk < 4; kk++) {
            const float* s0 = S[2 * kk];
            const float* s1 = S[2 * kk + 1];
            uint32_t PH[4], PL[4];
            PH[0] = packbf(s0[0], s0[1]);
            PH[1] = packbf(s0[2], s0[3]);
            PH[2] = packbf(s1[0], s1[1]);
            PH[3] = packbf(s1[2], s1[3]);
#pragma unroll
            for (int e = 0; e < 4; e++) {
                const float* sv = (e < 2) ? s0 : s1;
                float c0 = sv[(e & 1) * 2], c1 = sv[(e & 1) * 2 + 1];
                float f0 = __uint_as_float(PH[e] << 16);
                float f1 = __uint_as_float(PH[e] & 0xffff0000u);
                PL[e] = packbf(c0 - f0, c1 - f1);
            }
#pragma unroll
            for (int dc = 0; dc < 4; dc++) {
                uint32_t vo = (uint32_t)((kk * 16 + vrow_in) * SROW + dc * 16 + vcol_of) * 2;
                uint32_t vh0, vh1, vh2, vh3, vl0, vl1, vl2, vl3;
                ldmx4t(vh0, vh1, vh2, vh3, soff(buf, 2) + vo);
                ldmx4t(vl0, vl1, vl2, vl3, soff(buf, 3) + vo);
                mma16816(O[dc * 2 + 0], PH, vh0, vh1);
                mma16816(O[dc * 2 + 0], PL, vh0, vh1);
                mma16816(O[dc * 2 + 0], PH, vl0, vl1);
                mma16816(O[dc * 2 + 1], PH, vh2, vh3);
                mma16816(O[dc * 2 + 1], PL, vh2, vh3);
                mma16816(O[dc * 2 + 1], PH, vl2, vl3);
            }
        }
    }

    l0 += __shfl_xor_sync(0xffffffff, l0, 1);
    l0 += __shfl_xor_sync(0xffffffff, l0, 2);
    l1 += __shfl_xor_sync(0xffffffff, l1, 1);
    l1 += __shfl_xor_sync(0xffffffff, l1, 2);
    const float i0 = 1.f / l0, i1 = 1.f / l1;

    const int b = bh >> 4, h = bh & 15;
    const int t0 = q0 + wid * 16 + (lane >> 2);
    const int t1 = t0 + 8;
    const size_t co = (size_t)h * Dd + (lane & 3) * 2;
    __nv_bfloat16* ah0 = g_ah + ((size_t)(b * Tt + t0)) * Cc + co;
    __nv_bfloat16* al0 = g_al + ((size_t)(b * Tt + t0)) * Cc + co;
    __nv_bfloat16* ah1 = g_ah + ((size_t)(b * Tt + t1)) * Cc + co;
    __nv_bfloat16* al1 = g_al + ((size_t)(b * Tt + t1)) * Cc + co;
#pragma unroll
    for (int nf = 0; nf < 8; nf++) {
        float v0 = O[nf][0] * i0, v1 = O[nf][1] * i0;
        float v2 = O[nf][2] * i1, v3 = O[nf][3] * i1;
        __nv_bfloat16 h0 = __float2bfloat16(v0), h1 = __float2bfloat16(v1);
        __nv_bfloat16 h2 = __float2bfloat16(v2), h3 = __float2bfloat16(v3);
        __nv_bfloat162 w;
        w.x = h0; w.y = h1; *(__nv_bfloat162*)(ah0 + nf * 8) = w;
        w.x = h2; w.y = h3; *(__nv_bfloat162*)(ah1 + nf * 8) = w;
        w.x = __float2bfloat16(v0 - __bfloat162float(h0));
        w.y = __float2bfloat16(v1 - __bfloat162float(h1));
        *(__nv_bfloat162*)(al0 + nf * 8) = w;
        w.x = __float2bfloat16(v2 - __bfloat162float(h2));
        w.y = __float2bfloat16(v3 - __bfloat162float(h3));
        *(__nv_bfloat162*)(al1 + nf * 8) = w;
    }
}

// ---------------------------------------------------------------------------
extern "C" void kernel_launch(void* const* d_in, const int* in_sizes, int n_in,
                              void* d_out, int out_size)
{
    const float* x      = (const float*)d_in[0];
    const float* w_attn = (const float*)d_in[1];
    const float* b_attn = (const float*)d_in[2];
    const float* w_proj = (const float*)d_in[3];
    const float* b_proj = (const float*)d_in[4];
    const float* cosp   = (const float*)d_in[5];
    const float* sinp   = (const float*)d_in[6];
    float* out = (float*)d_out;

    void *p_xh, *p_xl, *p_wh, *p_wl, *p_ph, *p_pl, *p_ah, *p_al, *p_qkv;
    cudaGetSymbolAddress(&p_xh, g_xh);
    cudaGetSymbolAddress(&p_xl, g_xl);
    cudaGetSymbolAddress(&p_wh, g_wh);
    cudaGetSymbolAddress(&p_wl, g_wl);
    cudaGetSymbolAddress(&p_ph, g_ph);
    cudaGetSymbolAddress(&p_pl, g_pl);
    cudaGetSymbolAddress(&p_ah, g_ah);
    cudaGetSymbolAddress(&p_al, g_al);
    cudaGetSymbolAddress(&p_qkv, g_qkv);

    static bool once = false;
    if (!once) {
        cudaFuncSetAttribute(flash_mma,
                             cudaFuncAttributeMaxDynamicSharedMemorySize, 8 * TILE_B);
        cudaFuncSetAttribute(gemm_bf16x3,
                             cudaFuncAttributeMaxDynamicSharedMemorySize, GEMM_SMEM);
        cudaFuncSetAttribute(gemm_bf16x3,
                             cudaFuncAttributePreferredSharedMemoryCarveout, 100);
        once = true;
    }

    // 1) splits of x, w_attn, w_proj
    {
        int n4 = (Mtot * Cc) / 4;
        split_fp32_bf16<<<(n4 + 255) / 256, 256>>>(
            (const float4*)x, (__nv_bfloat162*)p_xh, (__nv_bfloat162*)p_xl, n4);
    }
    {
        int n4 = (3 * Cc * Cc) / 4;
        split_fp32_bf16<<<(n4 + 255) / 256, 256>>>(
            (const float4*)w_attn, (__nv_bfloat162*)p_wh, (__nv_bfloat162*)p_wl, n4);
    }
    {
        int n4 = (Cc * Cc) / 4;
        split_fp32_bf16<<<(n4 + 255) / 256, 256>>>(
            (const float4*)w_proj, (__nv_bfloat162*)p_ph, (__nv_bfloat162*)p_pl, n4);
    }

    // 2) QKV projection (pipelined tensor-core GEMM) -> g_qkv fp32
    {
        dim3 grid((3 * Cc) / 128, Mtot / 128);
        gemm_bf16x3<<<grid, 256, GEMM_SMEM>>>(
            (const __nv_bfloat16*)p_xh, (const __nv_bfloat16*)p_xl,
            (const __nv_bfloat16*)p_wh, (const __nv_bfloat16*)p_wl,
            b_attn, (float*)p_qkv, 3 * Cc, Cc);
    }

    // 3) fused RoPE + relayout + bf16 split of q,k,v
    {
        int total = Bb * Tt * NHh * 8;
        rope_split<<<total / 256, 256>>>(cosp, sinp);
    }

    // 4) flash attention -> g_ah/g_al bf16 (direct)
    {
        dim3 grid(Tt / 64, Bb * NHh);
        flash_mma<<<grid, 128, 8 * TILE_B>>>();
    }

    // 5) output projection
    {
        dim3 grid(Cc / 128, Mtot / 128);
        gemm_bf16x3<<<grid, 256, GEMM_SMEM>>>(
            (const __nv_bfloat16*)p_ah, (const __nv_bfloat16*)p_al,
            (const __nv_bfloat16*)p_ph, (const __nv_bfloat16*)p_pl,
            b_proj, out, Cc, Cc);
    }
}